// round 7
// baseline (speedup 1.0000x reference)
#include <cuda_runtime.h>
#include <cuda_fp16.h>
#include <cstdint>
#include <math.h>

#define N_NODES   20000
#define N_EDGES   320000
#define DIM       128
#define CODEBOOK_N 12000
#define CODEBOOK_PAD 12032
#define N_GRAPHS  256
#define N_LAYERS  5
#define BN_EPS    1e-5f
#define COMMIT_W  0.25f

// VQ (fp16 3-term split, K=384): A=[x_hi|x_lo|x_hi], B=[c_hi|c_hi|c_lo]
#define VQ_K       384
#define VQ_TILES   188             // CODEBOOK_PAD / 64
#define VQ_CPT     6               // k64 chunks per tile
#define VQ_CHUNKS  (VQ_TILES*VQ_CPT)
#define VQ_GRID    157             // ceil(20000/128)
#define VQ_MARGIN  0.02f
#define AS_STRIDE  392             // 384 + 8 halves
#define BS_STRIDE  72              // 64 + 8
#define BS_BUF_H   (64*BS_STRIDE)

typedef unsigned long long ull;

// ---------------- scratch ----------------
__device__ float g_z [N_NODES*DIM];
__device__ float g_t1[N_NODES*DIM];
__device__ float g_t2[N_NODES*DIM];
__device__ float g_h [N_NODES*DIM];
__device__ int   g_deg[N_NODES];
__device__ int   g_offs[N_NODES+1];
__device__ int   g_cursor[N_NODES];
__device__ int   g_csr[N_EDGES];
__device__ float g_stats[2*DIM];
__device__ float g_mean[DIM];
__device__ float g_invstd[DIM];
__device__ float g_cnorm[CODEBOOK_PAD];
__device__ int   g_idx[N_NODES];
__device__ float g_cacc[N_GRAPHS*DIM];
__device__ float g_sacc[N_GRAPHS*DIM];
__device__ float g_cmt[1];
__device__ __half g_cbs[(size_t)CODEBOOK_PAD * VQ_K];
__device__ int   g_flaglist[N_NODES];
__device__ int   g_flagcnt[1];
__device__ ull   g_best[N_NODES];

// ---------------- asm helpers ----------------
__device__ __forceinline__ uint32_t smem_u32(const void* p) {
    uint32_t a;
    asm("{ .reg .u64 t; cvta.to.shared.u64 t, %1; cvt.u32.u64 %0, t; }" : "=r"(a) : "l"(p));
    return a;
}
#define CP_ASYNC16(dst, src) \
    asm volatile("cp.async.cg.shared.global [%0], [%1], 16;" :: "r"(dst), "l"(src) : "memory")
#define CP_COMMIT() asm volatile("cp.async.commit_group;" ::: "memory")
#define CP_WAIT(n)  asm volatile("cp.async.wait_group %0;" :: "n"(n) : "memory")
#define LDSM4(r0,r1,r2,r3,addr) \
    asm volatile("ldmatrix.sync.aligned.m8n8.x4.shared.b16 {%0,%1,%2,%3}, [%4];" \
        : "=r"(r0), "=r"(r1), "=r"(r2), "=r"(r3) : "r"(addr))
#define MMA16816(d, a0,a1,a2,a3, b0,b1) \
    asm volatile("mma.sync.aligned.m16n8k16.row.col.f32.f16.f16.f32 " \
        "{%0,%1,%2,%3}, {%4,%5,%6,%7}, {%8,%9}, {%0,%1,%2,%3};" \
        : "+f"((d)[0]), "+f"((d)[1]), "+f"((d)[2]), "+f"((d)[3]) \
        : "r"(a0), "r"(a1), "r"(a2), "r"(a3), "r"(b0), "r"(b1))

__device__ __forceinline__ uint32_t fkey(float f) {
    uint32_t u = __float_as_uint(f);
    return (u & 0x80000000u) ? ~u : (u | 0x80000000u);
}
__device__ __forceinline__ void split16(float f, __half& hi, __half& lo) {
    hi = __float2half_rn(f);
    lo = __float2half_rn(f - __half2float(hi));
}

// ---------------- CSR build ----------------
__global__ void k_hist(const int* __restrict__ dst, int* __restrict__ deg) {
    int e = blockIdx.x * blockDim.x + threadIdx.x;
    if (e < N_EDGES) atomicAdd(&deg[dst[e]], 1);
}
__global__ void k_scan(const int* __restrict__ deg, int* __restrict__ offs) {
    __shared__ int sh[1024];
    __shared__ int carry;
    int tid = threadIdx.x;
    if (tid == 0) { carry = 0; offs[0] = 0; }
    __syncthreads();
    for (int base = 0; base < N_NODES; base += 1024) {
        int v = (base + tid < N_NODES) ? deg[base + tid] : 0;
        sh[tid] = v;
        __syncthreads();
        for (int o = 1; o < 1024; o <<= 1) {
            int t = (tid >= o) ? sh[tid - o] : 0;
            __syncthreads();
            sh[tid] += t;
            __syncthreads();
        }
        if (base + tid < N_NODES) offs[base + tid + 1] = carry + sh[tid];
        __syncthreads();
        if (tid == 0) carry += sh[1023];
        __syncthreads();
    }
}
__global__ void k_fill(const int* __restrict__ src, const int* __restrict__ dst,
                       int* __restrict__ cursor, int* __restrict__ csr) {
    int e = blockIdx.x * blockDim.x + threadIdx.x;
    if (e < N_EDGES) {
        int d = dst[e];
        int slot = atomicAdd(&cursor[d], 1);
        csr[slot] = src[e];
    }
}

// ---------------- aggregation ----------------
__global__ void k_agg(const float* __restrict__ h, const int* __restrict__ offs,
                      const int* __restrict__ csr, float* __restrict__ z) {
    int warp = (blockIdx.x * blockDim.x + threadIdx.x) >> 5;
    int lane = threadIdx.x & 31;
    if (warp >= N_NODES) return;
    const float4* hv = (const float4*)h;
    float4 acc = hv[warp * 32 + lane];
    float4 acc2 = make_float4(0.f, 0.f, 0.f, 0.f);
    int s = offs[warp], e = offs[warp + 1];
    int i = s;
    for (; i + 1 < e; i += 2) {
        int s0 = __ldg(&csr[i]);
        int s1 = __ldg(&csr[i + 1]);
        float4 v0 = hv[s0 * 32 + lane];
        float4 v1 = hv[s1 * 32 + lane];
        acc.x += v0.x;  acc.y += v0.y;  acc.z += v0.z;  acc.w += v0.w;
        acc2.x += v1.x; acc2.y += v1.y; acc2.z += v1.z; acc2.w += v1.w;
    }
    if (i < e) {
        float4 v = hv[__ldg(&csr[i]) * 32 + lane];
        acc.x += v.x; acc.y += v.y; acc.z += v.z; acc.w += v.w;
    }
    acc.x += acc2.x; acc.y += acc2.y; acc.z += acc2.z; acc.w += acc2.w;
    ((float4*)z)[warp * 32 + lane] = acc;
}

// ---------------- GEMM fp32 (R4-proven): out = relu?(A@W+b), opt BN stats --
__global__ __launch_bounds__(256) void k_gemm(
        const float* __restrict__ A, const float* __restrict__ W,
        const float* __restrict__ bias, float* __restrict__ out,
        int M, int doRelu, int doStats, float* __restrict__ stats) {
    __shared__ float As[64][32];
    __shared__ float Ws[32][128];
    int tid = threadIdx.x;
    int tx = tid & 31, ty = tid >> 5;
    int row0 = blockIdx.x * 64;
    float acc[8][4];
#pragma unroll
    for (int r = 0; r < 8; r++)
#pragma unroll
        for (int c = 0; c < 4; c++) acc[r][c] = 0.f;

    for (int kt = 0; kt < DIM; kt += 32) {
#pragma unroll
        for (int it = 0; it < 2; it++) {
            int i = tid + it * 256;
            int r = i >> 3, c4 = i & 7;
            int row = row0 + r;
            float4 v = make_float4(0.f, 0.f, 0.f, 0.f);
            if (row < M) v = *(const float4*)&A[row * DIM + kt + c4 * 4];
            *(float4*)&As[r][c4 * 4] = v;
        }
#pragma unroll
        for (int it = 0; it < 4; it++) {
            int i = tid + it * 256;
            int r = i >> 5, c4 = i & 31;
            *(float4*)&Ws[r][c4 * 4] = *(const float4*)&W[(kt + r) * DIM + c4 * 4];
        }
        __syncthreads();
#pragma unroll
        for (int k = 0; k < 32; k++) {
            float4 w = *(float4*)&Ws[k][tx * 4];
#pragma unroll
            for (int r = 0; r < 8; r++) {
                float a = As[ty * 8 + r][k];
                acc[r][0] += a * w.x;
                acc[r][1] += a * w.y;
                acc[r][2] += a * w.z;
                acc[r][3] += a * w.w;
            }
        }
        __syncthreads();
    }
    float4 b = *(const float4*)&bias[tx * 4];
    float s0 = 0.f, s1 = 0.f, s2 = 0.f, s3 = 0.f;
    float q0 = 0.f, q1 = 0.f, q2 = 0.f, q3 = 0.f;
#pragma unroll
    for (int r = 0; r < 8; r++) {
        int row = row0 + ty * 8 + r;
        if (row < M) {
            float v0 = acc[r][0] + b.x;
            float v1 = acc[r][1] + b.y;
            float v2 = acc[r][2] + b.z;
            float v3 = acc[r][3] + b.w;
            if (doRelu) {
                v0 = fmaxf(v0, 0.f); v1 = fmaxf(v1, 0.f);
                v2 = fmaxf(v2, 0.f); v3 = fmaxf(v3, 0.f);
            }
            *(float4*)&out[row * DIM + tx * 4] = make_float4(v0, v1, v2, v3);
            s0 += v0; s1 += v1; s2 += v2; s3 += v3;
            q0 += v0 * v0; q1 += v1 * v1; q2 += v2 * v2; q3 += v3 * v3;
        }
    }
    if (doStats) {
        atomicAdd(&stats[tx * 4 + 0], s0);
        atomicAdd(&stats[tx * 4 + 1], s1);
        atomicAdd(&stats[tx * 4 + 2], s2);
        atomicAdd(&stats[tx * 4 + 3], s3);
        atomicAdd(&stats[DIM + tx * 4 + 0], q0);
        atomicAdd(&stats[DIM + tx * 4 + 1], q1);
        atomicAdd(&stats[DIM + tx * 4 + 2], q2);
        atomicAdd(&stats[DIM + tx * 4 + 3], q3);
    }
}

// ---------------- batchnorm ----------------
__global__ void k_bnfin(const float* __restrict__ stats,
                        float* __restrict__ mean, float* __restrict__ invstd) {
    int d = threadIdx.x;
    float mu = stats[d] / (float)N_NODES;
    float var = stats[DIM + d] / (float)N_NODES - mu * mu;
    mean[d] = mu;
    invstd[d] = rsqrtf(var + BN_EPS);
}

__global__ void k_bnapply(const float* __restrict__ z, const float* __restrict__ mean,
                          const float* __restrict__ invstd, const float* __restrict__ gamma,
                          const float* __restrict__ beta, float* __restrict__ h) {
    int i = blockIdx.x * blockDim.x + threadIdx.x;
    if (i < N_NODES * DIM) {
        int d = i & (DIM - 1);
        h[i] = (z[i] - mean[d]) * invstd[d] * gamma[d] + beta[d];
    }
}

// ---------------- VQ: codebook norms ----------------
__global__ void k_cnorm(const float* __restrict__ cb, float* __restrict__ cnorm) {
    int warp = (blockIdx.x * blockDim.x + threadIdx.x) >> 5;
    int lane = threadIdx.x & 31;
    if (warp >= CODEBOOK_PAD) return;
    if (warp >= CODEBOOK_N) { if (lane == 0) cnorm[warp] = 1e30f; return; }
    float4 v = ((const float4*)cb)[warp * 32 + lane];
    float s = v.x * v.x + v.y * v.y + v.z * v.z + v.w * v.w;
#pragma unroll
    for (int o = 16; o; o >>= 1) s += __shfl_xor_sync(0xffffffffu, s, o);
    if (lane == 0) cnorm[warp] = s;
}

// ---------------- split codebook: [c_hi | c_hi | c_lo] fp16 ----------------
__global__ void k_split_cb(const float* __restrict__ cb, __half* __restrict__ cbs) {
    int gid = blockIdx.x * blockDim.x + threadIdx.x;
    if (gid >= CODEBOOK_PAD * DIM) return;
    int j = gid >> 7, d = gid & 127;
    float v = (j < CODEBOOK_N) ? cb[j * DIM + d] : 0.f;
    __half hi, lo; split16(v, hi, lo);
    __half* row = cbs + (size_t)j * VQ_K;
    row[d] = hi;
    row[128 + d] = hi;
    row[256 + d] = lo;
}

// ---------------- VQ main: fp16 3-term mma GEMM-argmin, M=128/block --------
__global__ __launch_bounds__(256, 1) void k_vq_mma(
        const float* __restrict__ h, const __half* __restrict__ cbs,
        const float* __restrict__ cnorm, int* __restrict__ outidx,
        int* __restrict__ flaglist, int* __restrict__ flagcnt) {
    extern __shared__ __align__(16) char dyn[];
    __half* As = (__half*)dyn;                 // [128][392]
    __half* Bs = As + 128 * AS_STRIDE;         // [4][64][72]
    float* cns = (float*)(Bs + 4 * BS_BUF_H);  // [64]
    float* rD1 = cns + 64;                     // [128][2]
    float* rD2 = rD1 + 256;
    int*   rJ1 = (int*)(rD2 + 256);
    uint32_t As_u = smem_u32(As);
    uint32_t Bs_u = smem_u32(Bs);

    int tid = threadIdx.x, lane = tid & 31, wid = tid >> 5;
    int warp_m = wid & 3, warp_n = wid >> 2;
    int node0 = blockIdx.x * 128;

    // ---- A: [x_hi | x_lo | x_hi]; 2 threads/row ----
    {
        int r = tid >> 1, q = tid & 1;
        bool valid = (node0 + r) < N_NODES;
        const float4* hp = (const float4*)(h + (size_t)(valid ? node0 + r : 0) * DIM);
        __half* arow = As + r * AS_STRIDE;
#pragma unroll
        for (int v = 0; v < 16; v++) {
            float4 f = valid ? hp[q * 16 + v] : make_float4(0.f, 0.f, 0.f, 0.f);
            __half hx, lx, hy, ly, hz, lz, hw, lw;
            split16(f.x, hx, lx); split16(f.y, hy, ly);
            split16(f.z, hz, lz); split16(f.w, hw, lw);
            int col = q * 64 + v * 4;
            arow[col + 0] = hx; arow[col + 1] = hy; arow[col + 2] = hz; arow[col + 3] = hw;
            arow[128 + col + 0] = lx; arow[128 + col + 1] = ly;
            arow[128 + col + 2] = lz; arow[128 + col + 3] = lw;
            arow[256 + col + 0] = hx; arow[256 + col + 1] = hy;
            arow[256 + col + 2] = hz; arow[256 + col + 3] = hw;
        }
    }

    // ---- preload chunks 0,1 ----
#pragma unroll
    for (int pc = 0; pc < 2; pc++) {
        const __half* base = cbs + (size_t)pc * 64;   // tile 0, chunk pc
#pragma unroll
        for (int it = 0; it < 2; it++) {
            int i = tid + it * 256;
            int row = i >> 3, c16 = i & 7;
            CP_ASYNC16(Bs_u + (uint32_t)(pc * BS_BUF_H + row * BS_STRIDE + c16 * 8) * 2,
                       base + (size_t)row * VQ_K + c16 * 8);
        }
        CP_COMMIT();
    }

    float d1v[2][2] = {{1e38f, 1e38f}, {1e38f, 1e38f}};
    float d2v[2][2] = {{1e38f, 1e38f}, {1e38f, 1e38f}};
    int   j1v[2][2] = {{0, 0}, {0, 0}};
    int lr = lane & 7, g = lane >> 3;
    float acc[2][4][4];

    for (int idx = 0; idx < VQ_CHUNKS; idx++) {
        int t = idx / VQ_CPT, c = idx % VQ_CPT;
        int buf = idx & 3;
        if (c == 0) {
#pragma unroll
            for (int mt = 0; mt < 2; mt++)
#pragma unroll
                for (int j = 0; j < 4; j++)
#pragma unroll
                    for (int r = 0; r < 4; r++) acc[mt][j][r] = 0.f;
        }
        if (idx + 2 < VQ_CHUNKS) {
            int pidx = idx + 2;
            int pbuf = pidx & 3;
            const __half* base = cbs + (size_t)(pidx / VQ_CPT) * 64 * VQ_K + (pidx % VQ_CPT) * 64;
#pragma unroll
            for (int it = 0; it < 2; it++) {
                int i = tid + it * 256;
                int row = i >> 3, c16 = i & 7;
                CP_ASYNC16(Bs_u + (uint32_t)(pbuf * BS_BUF_H + row * BS_STRIDE + c16 * 8) * 2,
                           base + (size_t)row * VQ_K + c16 * 8);
            }
            CP_COMMIT();
            CP_WAIT(2);
        } else {
            CP_WAIT(0);
        }
        __syncthreads();
        if (c == 0 && tid < 64) cns[tid] = __ldg(&cnorm[t * 64 + tid]);

        uint32_t bbase = Bs_u + (uint32_t)(buf * BS_BUF_H) * 2;
#pragma unroll
        for (int kk = 0; kk < 4; kk++) {
            int kcol = c * 64 + kk * 16;
            uint32_t a0[2], a1[2], a2[2], a3[2];
#pragma unroll
            for (int mt = 0; mt < 2; mt++) {
                uint32_t aaddr = As_u +
                    (uint32_t)((warp_m * 32 + mt * 16 + lr + ((g & 1) << 3)) * AS_STRIDE
                               + kcol + ((g >> 1) << 3)) * 2;
                LDSM4(a0[mt], a1[mt], a2[mt], a3[mt], aaddr);
            }
#pragma unroll
            for (int hn = 0; hn < 2; hn++) {
                uint32_t b0, b1, b2, b3;
                uint32_t baddr = bbase +
                    (uint32_t)((warp_n * 32 + hn * 16 + lr + ((g >> 1) << 3)) * BS_STRIDE
                               + kk * 16 + ((g & 1) << 3)) * 2;
                LDSM4(b0, b1, b2, b3, baddr);
#pragma unroll
                for (int mt = 0; mt < 2; mt++) {
                    MMA16816(acc[mt][hn * 2 + 0], a0[mt], a1[mt], a2[mt], a3[mt], b0, b1);
                    MMA16816(acc[mt][hn * 2 + 1], a0[mt], a1[mt], a2[mt], a3[mt], b2, b3);
                }
            }
        }
        if (c == VQ_CPT - 1) {
            int cb0 = warp_n * 32;
            int lcol = 2 * (lane & 3);
#pragma unroll
            for (int j = 0; j < 4; j++) {
                int cloc = cb0 + j * 8 + lcol;
                float cn0 = cns[cloc], cn1 = cns[cloc + 1];
                int code = t * 64 + cloc;
#pragma unroll
                for (int mt = 0; mt < 2; mt++)
#pragma unroll
                    for (int rs = 0; rs < 2; rs++) {
                        float dA = cn0 - 2.f * acc[mt][j][rs * 2 + 0];
                        float dB = cn1 - 2.f * acc[mt][j][rs * 2 + 1];
                        if (dA < d1v[mt][rs]) { d2v[mt][rs] = d1v[mt][rs]; d1v[mt][rs] = dA; j1v[mt][rs] = code; }
                        else if (dA < d2v[mt][rs]) d2v[mt][rs] = dA;
                        if (dB < d1v[mt][rs]) { d2v[mt][rs] = d1v[mt][rs]; d1v[mt][rs] = dB; j1v[mt][rs] = code + 1; }
                        else if (dB < d2v[mt][rs]) d2v[mt][rs] = dB;
                    }
            }
        }
    }

#pragma unroll
    for (int o = 1; o <= 2; o <<= 1) {
#pragma unroll
        for (int mt = 0; mt < 2; mt++)
#pragma unroll
            for (int rs = 0; rs < 2; rs++) {
                float od1 = __shfl_xor_sync(0xffffffffu, d1v[mt][rs], o);
                float od2 = __shfl_xor_sync(0xffffffffu, d2v[mt][rs], o);
                int   oj  = __shfl_xor_sync(0xffffffffu, j1v[mt][rs], o);
                if (od1 < d1v[mt][rs] || (od1 == d1v[mt][rs] && oj < j1v[mt][rs])) {
                    d2v[mt][rs] = fminf(d1v[mt][rs], od2);
                    d1v[mt][rs] = od1; j1v[mt][rs] = oj;
                } else {
                    d2v[mt][rs] = fminf(d2v[mt][rs], od1);
                }
            }
    }
    __syncthreads();
    if ((lane & 3) == 0) {
#pragma unroll
        for (int mt = 0; mt < 2; mt++)
#pragma unroll
            for (int rs = 0; rs < 2; rs++) {
                int nl = warp_m * 32 + mt * 16 + rs * 8 + (lane >> 2);
                rD1[nl * 2 + warp_n] = d1v[mt][rs];
                rD2[nl * 2 + warp_n] = d2v[mt][rs];
                rJ1[nl * 2 + warp_n] = j1v[mt][rs];
            }
    }
    __syncthreads();
    if (tid < 128) {
        float a1 = rD1[tid * 2], a2 = rD2[tid * 2];
        int aj = rJ1[tid * 2];
        float b1 = rD1[tid * 2 + 1], b2 = rD2[tid * 2 + 1];
        int bj = rJ1[tid * 2 + 1];
        float f1, f2; int fj;
        if (b1 < a1 || (b1 == a1 && bj < aj)) { f1 = b1; fj = bj; f2 = fminf(a1, b2); }
        else { f1 = a1; fj = aj; f2 = fminf(a2, b1); }
        int node = node0 + tid;
        if (node < N_NODES) {
            outidx[node] = fj;
            if (f2 - f1 < VQ_MARGIN) {
                int p = atomicAdd(flagcnt, 1);
                flaglist[p] = node;
            }
        }
    }
}

// ---------------- exact fp32 rescue ----------------
__global__ __launch_bounds__(128) void k_rescue(
        const float* __restrict__ h, const float* __restrict__ cb,
        const float* __restrict__ cnorm, const int* __restrict__ flaglist,
        const int* __restrict__ flagcnt, ull* __restrict__ best) {
    extern __shared__ __align__(16) float rs[];
    float* cs   = rs;
    float* hrow = cs + 128 * 128;
    float* rd   = hrow + 128;
    int*   rj   = (int*)(rd + 128);
    int tid = threadIdx.x;
    int c0 = blockIdx.x * 128;
    int code = c0 + tid;
#pragma unroll
    for (int it = 0; it < 32; it++) {
        int i = tid + it * 128;
        int row = i >> 5, c4 = i & 31;
        float4 v = make_float4(0.f, 0.f, 0.f, 0.f);
        if (c0 + row < CODEBOOK_N) v = __ldg(&((const float4*)cb)[(size_t)(c0 + row) * 32 + c4]);
        *(float4*)&cs[row * 128 + c4 * 4] = v;
    }
    float cn = cnorm[code];
    __syncthreads();
    int cnt = *flagcnt;
    const float4* crow4 = (const float4*)&cs[tid * 128];
    const float4* h4 = (const float4*)hrow;
    for (int f = 0; f < cnt; f++) {
        int node = flaglist[f];
        if (tid < 32) ((float4*)hrow)[tid] = ((const float4*)(h + (size_t)node * DIM))[tid];
        __syncthreads();
        float dot = 0.f;
#pragma unroll
        for (int k4 = 0; k4 < 32; k4++) {
            int i = (k4 + tid) & 31;
            float4 cv = crow4[i];
            float4 hv = h4[i];
            dot += cv.x * hv.x + cv.y * hv.y + cv.z * hv.z + cv.w * hv.w;
        }
        float d = cn - 2.f * dot;
        rd[tid] = d; rj[tid] = code;
        __syncthreads();
        for (int o = 64; o; o >>= 1) {
            if (tid < o) {
                float od = rd[tid + o]; int oc = rj[tid + o];
                if (od < rd[tid] || (od == rd[tid] && oc < rj[tid])) {
                    rd[tid] = od; rj[tid] = oc;
                }
            }
            __syncthreads();
        }
        if (tid == 0) {
            ull key = ((ull)fkey(rd[0]) << 32) | (uint32_t)rj[0];
            atomicMin(&best[node], key);
        }
        __syncthreads();
    }
}

__global__ void k_flagapply(const int* __restrict__ flaglist, const int* __restrict__ flagcnt,
                            const ull* __restrict__ best, int* __restrict__ outidx) {
    int cnt = *flagcnt;
    for (int i = blockIdx.x * blockDim.x + threadIdx.x; i < cnt; i += gridDim.x * blockDim.x) {
        int node = flaglist[i];
        outidx[node] = (int)(best[node] & 0xFFFFFFFFull);
    }
}

// ---------------- final per-node ----------------
__global__ void k_final(const float* __restrict__ h, const float* __restrict__ cb,
                        const int* __restrict__ idx, const float* __restrict__ score,
                        const int* __restrict__ batch, float* __restrict__ cacc,
                        float* __restrict__ sacc, float* __restrict__ cmt) {
    __shared__ float sh[256];
    int i = blockIdx.x * blockDim.x + threadIdx.x;
    float local = 0.f;
    if (i < N_NODES * DIM) {
        int node = i >> 7, d = i & 127;
        float hv = h[i];
        float q = cb[idx[node] * DIM + d];
        float diff = q - hv;
        local = diff * diff;
        float res = hv + q;
        float sc = score[node];
        int b = batch[node];
        atomicAdd(&cacc[b * DIM + d], res * sc);
        atomicAdd(&sacc[b * DIM + d], res * (1.f - sc));
    }
    sh[threadIdx.x] = local;
    __syncthreads();
    for (int o = 128; o; o >>= 1) {
        if (threadIdx.x < o) sh[threadIdx.x] += sh[threadIdx.x + o];
        __syncthreads();
    }
    if (threadIdx.x == 0) atomicAdd(cmt, sh[0]);
}

__global__ void k_cmtfin(const float* __restrict__ cmt, float* __restrict__ out) {
    out[2 * N_GRAPHS * DIM] = COMMIT_W * cmt[0] / (float)(N_NODES * DIM);
}

// ---------------- launcher ----------------
extern "C" void kernel_launch(void* const* d_in, const int* in_sizes, int n_in,
                              void* d_out, int out_size) {
    const float* x        = (const float*)d_in[0];
    const int*   ei       = (const int*)  d_in[1];
    const int*   batch    = (const int*)  d_in[2];
    const float* score    = (const float*)d_in[3];
    const float* cW1      = (const float*)d_in[4];
    const float* cb1      = (const float*)d_in[5];
    const float* cW2      = (const float*)d_in[6];
    const float* cb2      = (const float*)d_in[7];
    const float* bng      = (const float*)d_in[8];
    const float* bnb      = (const float*)d_in[9];
    const float* codebook = (const float*)d_in[10];
    const float* fc1W     = (const float*)d_in[11];
    const float* fc1b     = (const float*)d_in[12];
    const float* fc2W     = (const float*)d_in[13];
    const float* fc2b     = (const float*)d_in[14];
    float* out = (float*)d_out;
    const int* src = ei;
    const int* dst = ei + N_EDGES;

    void *p_z, *p_t1, *p_t2, *p_h, *p_deg, *p_offs, *p_cursor, *p_csr;
    void *p_stats, *p_mean, *p_invstd, *p_cnorm, *p_idx, *p_cacc, *p_sacc, *p_cmt;
    void *p_cbs, *p_flag, *p_fcnt, *p_best;
    cudaGetSymbolAddress(&p_z, g_z);
    cudaGetSymbolAddress(&p_t1, g_t1);
    cudaGetSymbolAddress(&p_t2, g_t2);
    cudaGetSymbolAddress(&p_h, g_h);
    cudaGetSymbolAddress(&p_deg, g_deg);
    cudaGetSymbolAddress(&p_offs, g_offs);
    cudaGetSymbolAddress(&p_cursor, g_cursor);
    cudaGetSymbolAddress(&p_csr, g_csr);
    cudaGetSymbolAddress(&p_stats, g_stats);
    cudaGetSymbolAddress(&p_mean, g_mean);
    cudaGetSymbolAddress(&p_invstd, g_invstd);
    cudaGetSymbolAddress(&p_cnorm, g_cnorm);
    cudaGetSymbolAddress(&p_idx, g_idx);
    cudaGetSymbolAddress(&p_cacc, g_cacc);
    cudaGetSymbolAddress(&p_sacc, g_sacc);
    cudaGetSymbolAddress(&p_cmt, g_cmt);
    cudaGetSymbolAddress(&p_cbs, g_cbs);
    cudaGetSymbolAddress(&p_flag, g_flaglist);
    cudaGetSymbolAddress(&p_fcnt, g_flagcnt);
    cudaGetSymbolAddress(&p_best, g_best);

    const int SMEM_VQ = 128 * AS_STRIDE * 2 + 4 * BS_BUF_H * 2 + 64 * 4 + 256 * 4 * 3;
    const int SMEM_RESCUE = 128 * 128 * 4 + 128 * 4 * 3;
    static bool attr_set = false;
    if (!attr_set) {
        cudaFuncSetAttribute(k_vq_mma, cudaFuncAttributeMaxDynamicSharedMemorySize, SMEM_VQ);
        cudaFuncSetAttribute(k_rescue, cudaFuncAttributeMaxDynamicSharedMemorySize, SMEM_RESCUE);
        attr_set = true;
    }

    // CSR build
    cudaMemsetAsync(p_deg, 0, N_NODES * sizeof(int));
    k_hist<<<(N_EDGES + 255) / 256, 256>>>(dst, (int*)p_deg);
    k_scan<<<1, 1024>>>((const int*)p_deg, (int*)p_offs);
    cudaMemcpyAsync(p_cursor, p_offs, N_NODES * sizeof(int), cudaMemcpyDeviceToDevice);
    k_fill<<<(N_EDGES + 255) / 256, 256>>>(src, dst, (int*)p_cursor, (int*)p_csr);

    // codebook prep (independent of h)
    k_cnorm<<<(CODEBOOK_PAD * 32 + 255) / 256, 256>>>(codebook, (float*)p_cnorm);
    k_split_cb<<<(CODEBOOK_PAD * DIM + 255) / 256, 256>>>(codebook, (__half*)p_cbs);

    // MLP chain: fp32 GEMMs (R4-proven — h must be fp32-accurate for VQ ties)
    const int gemmBlocks = (N_NODES + 63) / 64;
    const float* h = x;
    for (int l = 0; l < N_LAYERS; l++) {
        k_agg<<<(N_NODES * 32 + 255) / 256, 256>>>(h, (const int*)p_offs,
                                                   (const int*)p_csr, (float*)p_z);
        k_gemm<<<gemmBlocks, 256>>>((const float*)p_z, cW1 + l * DIM * DIM, cb1 + l * DIM,
                                    (float*)p_t1, N_NODES, 1, 0, nullptr);
        cudaMemsetAsync(p_stats, 0, 2 * DIM * sizeof(float));
        k_gemm<<<gemmBlocks, 256>>>((const float*)p_t1, cW2 + l * DIM * DIM, cb2 + l * DIM,
                                    (float*)p_t2, N_NODES, 1, 1, (float*)p_stats);
        k_bnfin<<<1, 128>>>((const float*)p_stats, (float*)p_mean, (float*)p_invstd);
        k_bnapply<<<(N_NODES * DIM + 255) / 256, 256>>>(
            (const float*)p_t2, (const float*)p_mean, (const float*)p_invstd,
            bng + l * DIM, bnb + l * DIM, (float*)p_h);
        h = (const float*)p_h;
    }

    // VQ search (fp16 3-term tensor cores) + exact rescue
    cudaMemsetAsync(p_fcnt, 0, sizeof(int));
    cudaMemsetAsync(p_best, 0xFF, N_NODES * sizeof(ull));
    k_vq_mma<<<VQ_GRID, 256, SMEM_VQ>>>((const float*)p_h, (const __half*)p_cbs,
                                        (const float*)p_cnorm, (int*)p_idx,
                                        (int*)p_flag, (int*)p_fcnt);
    k_rescue<<<CODEBOOK_PAD / 128, 128, SMEM_RESCUE>>>(
        (const float*)p_h, codebook, (const float*)p_cnorm,
        (const int*)p_flag, (const int*)p_fcnt, (ull*)p_best);
    k_flagapply<<<40, 256>>>((const int*)p_flag, (const int*)p_fcnt,
                             (const ull*)p_best, (int*)p_idx);

    cudaMemsetAsync(p_cacc, 0, N_GRAPHS * DIM * sizeof(float));
    cudaMemsetAsync(p_sacc, 0, N_GRAPHS * DIM * sizeof(float));
    cudaMemsetAsync(p_cmt, 0, sizeof(float));
    k_final<<<(N_NODES * DIM + 255) / 256, 256>>>(
        (const float*)p_h, codebook, (const int*)p_idx, score, batch,
        (float*)p_cacc, (float*)p_sacc, (float*)p_cmt);

    k_gemm<<<(N_GRAPHS + 63) / 64, 256>>>((const float*)p_cacc, fc1W, fc1b,
                                          out, N_GRAPHS, 1, 0, nullptr);
    k_gemm<<<(N_GRAPHS + 63) / 64, 256>>>((const float*)p_sacc, fc2W, fc2b,
                                          out + N_GRAPHS * DIM, N_GRAPHS, 1, 0, nullptr);
    k_cmtfin<<<1, 1>>>((const float*)p_cmt, out);
}

// round 12
// speedup vs baseline: 1.5371x; 1.5371x over previous
#include <cuda_runtime.h>
#include <cuda_fp16.h>
#include <cstdint>
#include <math.h>

#define N_NODES   20000
#define N_EDGES   320000
#define DIM       128
#define CODEBOOK_N 12000
#define CODEBOOK_PAD 12032
#define N_GRAPHS  256
#define N_LAYERS  5
#define BN_EPS    1e-5f
#define COMMIT_W  0.25f
#define STAT_BLOCKS 157

// VQ: exact fp16 3-term product via pass pairing (R8 machinery).
#define VQ_K       256
#define VQ_TILES   188
#define VQ_CPT     4
#define VQ_CHUNKS  (VQ_TILES*VQ_CPT)
#define VQ_GRID    313
#define VQ_MARGIN  0.02f
#define AS_STRIDE  264
#define BS_STRIDE  72
#define BS_BUF_H   (64*BS_STRIDE)

typedef unsigned long long ull;

// ---------------- scratch ----------------
__device__ float g_z [N_NODES*DIM];
__device__ float g_t1[N_NODES*DIM];
__device__ float g_t2[N_NODES*DIM];
__device__ float g_h [N_NODES*DIM];
__device__ int   g_deg[N_NODES];
__device__ int   g_offs[N_NODES+1];
__device__ int   g_cursor[N_NODES];
__device__ ull   g_csrk[N_EDGES];   // (edge_idx<<32)|src — sorted per node = edge order
__device__ float g_pstats[STAT_BLOCKS*2*DIM];
__device__ float g_mean[DIM];
__device__ float g_invstd[DIM];
__device__ float g_cnorm[CODEBOOK_PAD];
__device__ int   g_idx[N_NODES];
__device__ float g_cacc[N_GRAPHS*DIM];
__device__ float g_sacc[N_GRAPHS*DIM];
__device__ float g_cmt[1];
__device__ __half g_cbs[(size_t)CODEBOOK_PAD * VQ_K];
__device__ int   g_flaglist[N_NODES];
__device__ int   g_flagcnt[1];
__device__ ull   g_best[N_NODES];

// ---------------- asm helpers ----------------
__device__ __forceinline__ uint32_t smem_u32(const void* p) {
    uint32_t a;
    asm("{ .reg .u64 t; cvta.to.shared.u64 t, %1; cvt.u32.u64 %0, t; }" : "=r"(a) : "l"(p));
    return a;
}
#define CP_ASYNC16(dst, src) \
    asm volatile("cp.async.cg.shared.global [%0], [%1], 16;" :: "r"(dst), "l"(src) : "memory")
#define CP_COMMIT() asm volatile("cp.async.commit_group;" ::: "memory")
#define CP_WAIT(n)  asm volatile("cp.async.wait_group %0;" :: "n"(n) : "memory")
#define LDSM4(r0,r1,r2,r3,addr) \
    asm volatile("ldmatrix.sync.aligned.m8n8.x4.shared.b16 {%0,%1,%2,%3}, [%4];" \
        : "=r"(r0), "=r"(r1), "=r"(r2), "=r"(r3) : "r"(addr))
#define MMA16816(d, a0,a1,a2,a3, b0,b1) \
    asm volatile("mma.sync.aligned.m16n8k16.row.col.f32.f16.f16.f32 " \
        "{%0,%1,%2,%3}, {%4,%5,%6,%7}, {%8,%9}, {%0,%1,%2,%3};" \
        : "+f"((d)[0]), "+f"((d)[1]), "+f"((d)[2]), "+f"((d)[3]) \
        : "r"(a0), "r"(a1), "r"(a2), "r"(a3), "r"(b0), "r"(b1))

__device__ __forceinline__ uint32_t fkey(float f) {
    uint32_t u = __float_as_uint(f);
    return (u & 0x80000000u) ? ~u : (u | 0x80000000u);
}
__device__ __forceinline__ void split16(float f, __half& hi, __half& lo) {
    hi = __float2half_rn(f);
    lo = __float2half_rn(f - __half2float(hi));
}

// ---------------- CSR build: edge-order deterministic ----------------------
__global__ void k_hist(const int* __restrict__ dst, int* __restrict__ deg) {
    int e = blockIdx.x * blockDim.x + threadIdx.x;
    if (e < N_EDGES) atomicAdd(&deg[dst[e]], 1);
}
__global__ void k_scan(const int* __restrict__ deg, int* __restrict__ offs) {
    __shared__ int sh[1024];
    __shared__ int carry;
    int tid = threadIdx.x;
    if (tid == 0) { carry = 0; offs[0] = 0; }
    __syncthreads();
    for (int base = 0; base < N_NODES; base += 1024) {
        int v = (base + tid < N_NODES) ? deg[base + tid] : 0;
        sh[tid] = v;
        __syncthreads();
        for (int o = 1; o < 1024; o <<= 1) {
            int t = (tid >= o) ? sh[tid - o] : 0;
            __syncthreads();
            sh[tid] += t;
            __syncthreads();
        }
        if (base + tid < N_NODES) offs[base + tid + 1] = carry + sh[tid];
        __syncthreads();
        if (tid == 0) carry += sh[1023];
        __syncthreads();
    }
}
__global__ void k_fill(const int* __restrict__ src, const int* __restrict__ dst,
                       int* __restrict__ cursor, ull* __restrict__ csrk) {
    int e = blockIdx.x * blockDim.x + threadIdx.x;
    if (e < N_EDGES) {
        int d = dst[e];
        int slot = atomicAdd(&cursor[d], 1);
        csrk[slot] = ((ull)(uint32_t)e << 32) | (uint32_t)src[e];
    }
}
// sort each segment by edge index (high bits) -> exact edge-order summation
__global__ void k_sortcsr(const int* __restrict__ offs, ull* __restrict__ csrk) {
    int n = blockIdx.x * blockDim.x + threadIdx.x;
    if (n >= N_NODES) return;
    int s = offs[n], e = offs[n + 1];
    for (int i = s + 1; i < e; i++) {
        ull v = csrk[i];
        int j = i - 1;
        while (j >= s && csrk[j] > v) { csrk[j + 1] = csrk[j]; j--; }
        csrk[j + 1] = v;
    }
}

// ---------------- aggregation: fp32, edge order (matches golden) ----------
__global__ void k_agg(const float* __restrict__ h, const int* __restrict__ offs,
                      const ull* __restrict__ csrk, float* __restrict__ z) {
    int warp = (blockIdx.x * blockDim.x + threadIdx.x) >> 5;
    int lane = threadIdx.x & 31;
    if (warp >= N_NODES) return;
    const float4* hv = (const float4*)h;
    float4 acc = hv[warp * 32 + lane];
    int s = offs[warp], e = offs[warp + 1];
    for (int i = s; i < e; i++) {
        int sidx = (int)(uint32_t)(__ldg(&csrk[i]) & 0xFFFFFFFFull);
        float4 v = hv[sidx * 32 + lane];
        acc.x += v.x; acc.y += v.y; acc.z += v.z; acc.w += v.w;
    }
    ((float4*)z)[warp * 32 + lane] = acc;
}

// ---------------- GEMM fp32 (R4/R7-proven, bit-identical): ----------------
__global__ __launch_bounds__(256) void k_gemm(
        const float* __restrict__ A, const float* __restrict__ W,
        const float* __restrict__ bias, float* __restrict__ out,
        int M, int doRelu) {
    __shared__ float As[64][32];
    __shared__ float Ws[32][128];
    int tid = threadIdx.x;
    int tx = tid & 31, ty = tid >> 5;
    int row0 = blockIdx.x * 64;
    float acc[8][4];
#pragma unroll
    for (int r = 0; r < 8; r++)
#pragma unroll
        for (int c = 0; c < 4; c++) acc[r][c] = 0.f;

    for (int kt = 0; kt < DIM; kt += 32) {
#pragma unroll
        for (int it = 0; it < 2; it++) {
            int i = tid + it * 256;
            int r = i >> 3, c4 = i & 7;
            int row = row0 + r;
            float4 v = make_float4(0.f, 0.f, 0.f, 0.f);
            if (row < M) v = *(const float4*)&A[row * DIM + kt + c4 * 4];
            *(float4*)&As[r][c4 * 4] = v;
        }
#pragma unroll
        for (int it = 0; it < 4; it++) {
            int i = tid + it * 256;
            int r = i >> 5, c4 = i & 31;
            *(float4*)&Ws[r][c4 * 4] = *(const float4*)&W[(kt + r) * DIM + c4 * 4];
        }
        __syncthreads();
#pragma unroll
        for (int k = 0; k < 32; k++) {
            float4 w = *(float4*)&Ws[k][tx * 4];
#pragma unroll
            for (int r = 0; r < 8; r++) {
                float a = As[ty * 8 + r][k];
                acc[r][0] += a * w.x;
                acc[r][1] += a * w.y;
                acc[r][2] += a * w.z;
                acc[r][3] += a * w.w;
            }
        }
        __syncthreads();
    }
    float4 b = *(const float4*)&bias[tx * 4];
#pragma unroll
    for (int r = 0; r < 8; r++) {
        int row = row0 + ty * 8 + r;
        if (row < M) {
            float v0 = acc[r][0] + b.x;
            float v1 = acc[r][1] + b.y;
            float v2 = acc[r][2] + b.z;
            float v3 = acc[r][3] + b.w;
            if (doRelu) {
                v0 = fmaxf(v0, 0.f); v1 = fmaxf(v1, 0.f);
                v2 = fmaxf(v2, 0.f); v3 = fmaxf(v3, 0.f);
            }
            *(float4*)&out[row * DIM + tx * 4] = make_float4(v0, v1, v2, v3);
        }
    }
}

// ---------------- BN stats: deterministic fp32 per-block partials ---------
__global__ void k_stats(const float* __restrict__ t2, float* __restrict__ pstats) {
    __shared__ float ss[256], qq[256];
    int tid = threadIdx.x;
    int col = tid & 127, half = tid >> 7;
    float s = 0.f, q = 0.f;
    int row0 = blockIdx.x * 128;
    for (int i = half; i < 128; i += 2) {
        int r = row0 + i;
        if (r < N_NODES) {
            float v = t2[(size_t)r * DIM + col];
            s += v; q += v * v;
        }
    }
    ss[tid] = s; qq[tid] = q;
    __syncthreads();
    if (tid < 128) {
        pstats[blockIdx.x * 256 + tid]       = ss[tid] + ss[tid + 128];
        pstats[blockIdx.x * 256 + 128 + tid] = qq[tid] + qq[tid + 128];
    }
}

__global__ void k_bnfin(const float* __restrict__ pstats,
                        float* __restrict__ mean, float* __restrict__ invstd) {
    int d = threadIdx.x;
    float s = 0.f, q = 0.f;
    for (int b = 0; b < STAT_BLOCKS; b++) {
        s += pstats[b * 256 + d];
        q += pstats[b * 256 + 128 + d];
    }
    float mu = s / (float)N_NODES;
    float var = q / (float)N_NODES - mu * mu;
    mean[d] = mu;
    invstd[d] = rsqrtf(var + BN_EPS);
}

__global__ void k_bnapply(const float* __restrict__ z, const float* __restrict__ mean,
                          const float* __restrict__ invstd, const float* __restrict__ gamma,
                          const float* __restrict__ beta, float* __restrict__ h) {
    int i = blockIdx.x * blockDim.x + threadIdx.x;
    if (i < N_NODES * DIM) {
        int d = i & (DIM - 1);
        h[i] = (z[i] - mean[d]) * invstd[d] * gamma[d] + beta[d];
    }
}

// ---------------- VQ: codebook norms ----------------
__global__ void k_cnorm(const float* __restrict__ cb, float* __restrict__ cnorm) {
    int warp = (blockIdx.x * blockDim.x + threadIdx.x) >> 5;
    int lane = threadIdx.x & 31;
    if (warp >= CODEBOOK_PAD) return;
    if (warp >= CODEBOOK_N) { if (lane == 0) cnorm[warp] = 1e30f; return; }
    float4 v = ((const float4*)cb)[warp * 32 + lane];
    float s = v.x * v.x + v.y * v.y + v.z * v.z + v.w * v.w;
#pragma unroll
    for (int o = 16; o; o >>= 1) s += __shfl_xor_sync(0xffffffffu, s, o);
    if (lane == 0) cnorm[warp] = s;
}

// ---------------- split codebook: [c_hi | c_lo] fp16, K=256 ----------------
__global__ void k_split_cb(const float* __restrict__ cb, __half* __restrict__ cbs) {
    int gid = blockIdx.x * blockDim.x + threadIdx.x;
    if (gid >= CODEBOOK_PAD * DIM) return;
    int j = gid >> 7, d = gid & 127;
    float v = (j < CODEBOOK_N) ? cb[j * DIM + d] : 0.f;
    __half hi, lo; split16(v, hi, lo);
    __half* row = cbs + (size_t)j * VQ_K;
    row[d] = hi;
    row[128 + d] = lo;
}

// ---------------- VQ main: fp16 3-term GEMM-argmin, M=64/block, occ 2 ------
__global__ __launch_bounds__(256, 2) void k_vq_mma(
        const float* __restrict__ h, const __half* __restrict__ cbs,
        const float* __restrict__ cnorm, int* __restrict__ outidx,
        int* __restrict__ flaglist, int* __restrict__ flagcnt) {
    extern __shared__ __align__(16) char dyn[];
    __half* As = (__half*)dyn;                 // [64][264]
    __half* Bs = As + 64 * AS_STRIDE;          // [4][64][72]
    float* cns = (float*)(Bs + 4 * BS_BUF_H);  // [64]
    float* rD1 = cns + 64;                     // [64][4]
    float* rD2 = rD1 + 256;
    int*   rJ1 = (int*)(rD2 + 256);
    uint32_t As_u = smem_u32(As);
    uint32_t Bs_u = smem_u32(Bs);

    int tid = threadIdx.x, lane = tid & 31, wid = tid >> 5;
    int warp_m = wid & 1, warp_n = wid >> 1;   // 2m x 4n
    int node0 = blockIdx.x * 64;

    // ---- A: [x_hi | x_lo]; 4 threads/row ----
    {
        int r = tid >> 2, q = tid & 3;
        bool valid = (node0 + r) < N_NODES;
        const float4* hp = (const float4*)(h + (size_t)(valid ? node0 + r : 0) * DIM);
        __half* arow = As + r * AS_STRIDE;
#pragma unroll
        for (int v = 0; v < 8; v++) {
            float4 f = valid ? hp[q * 8 + v] : make_float4(0.f, 0.f, 0.f, 0.f);
            __half hx, lx, hy, ly, hz, lz, hw, lw;
            split16(f.x, hx, lx); split16(f.y, hy, ly);
            split16(f.z, hz, lz); split16(f.w, hw, lw);
            int col = q * 32 + v * 4;
            arow[col + 0] = hx; arow[col + 1] = hy; arow[col + 2] = hz; arow[col + 3] = hw;
            arow[128 + col + 0] = lx; arow[128 + col + 1] = ly;
            arow[128 + col + 2] = lz; arow[128 + col + 3] = lw;
        }
    }

    // ---- preload chunks 0,1 (tile 0) ----
#pragma unroll
    for (int pc = 0; pc < 2; pc++) {
        const __half* base = cbs + (size_t)pc * 64;
#pragma unroll
        for (int it = 0; it < 2; it++) {
            int i = tid + it * 256;
            int row = i >> 3, c16 = i & 7;
            CP_ASYNC16(Bs_u + (uint32_t)(pc * BS_BUF_H + row * BS_STRIDE + c16 * 8) * 2,
                       base + (size_t)row * VQ_K + c16 * 8);
        }
        CP_COMMIT();
    }

    float d1v[2][2] = {{1e38f, 1e38f}, {1e38f, 1e38f}};
    float d2v[2][2] = {{1e38f, 1e38f}, {1e38f, 1e38f}};
    int   j1v[2][2] = {{0, 0}, {0, 0}};
    int lr = lane & 7, g = lane >> 3;
    float acc[2][2][4];

    for (int idx = 0; idx < VQ_CHUNKS; idx++) {
        int t = idx >> 2, c = idx & 3;
        int buf = idx & 3;
        if (c == 0) {
#pragma unroll
            for (int mt = 0; mt < 2; mt++)
#pragma unroll
                for (int hf = 0; hf < 2; hf++)
#pragma unroll
                    for (int r = 0; r < 4; r++) acc[mt][hf][r] = 0.f;
        }
        if (idx + 2 < VQ_CHUNKS) {
            int pidx = idx + 2;
            int pbuf = pidx & 3;
            const __half* base = cbs + (size_t)(pidx >> 2) * 64 * VQ_K + (pidx & 3) * 64;
#pragma unroll
            for (int it = 0; it < 2; it++) {
                int i = tid + it * 256;
                int row = i >> 3, c16 = i & 7;
                CP_ASYNC16(Bs_u + (uint32_t)(pbuf * BS_BUF_H + row * BS_STRIDE + c16 * 8) * 2,
                           base + (size_t)row * VQ_K + c16 * 8);
            }
            CP_COMMIT();
            CP_WAIT(2);
        } else {
            CP_WAIT(0);
        }
        __syncthreads();
        if (c == 0 && tid < 64) cns[tid] = __ldg(&cnorm[t * 64 + tid]);

        uint32_t bbase = Bs_u + (uint32_t)(buf * BS_BUF_H) * 2;
        if (c < 2) {
            // c_hi chunk: pair with x_hi AND x_lo
#pragma unroll
            for (int kk = 0; kk < 4; kk++) {
                int kcol = c * 64 + kk * 16;
                uint32_t ah0[2], ah1[2], ah2[2], ah3[2];
                uint32_t al0[2], al1[2], al2[2], al3[2];
#pragma unroll
                for (int mt = 0; mt < 2; mt++) {
                    uint32_t abase = As_u +
                        (uint32_t)((warp_m * 32 + mt * 16 + lr + ((g & 1) << 3)) * AS_STRIDE
                                   + kcol + ((g >> 1) << 3)) * 2;
                    LDSM4(ah0[mt], ah1[mt], ah2[mt], ah3[mt], abase);
                    LDSM4(al0[mt], al1[mt], al2[mt], al3[mt], abase + 128 * 2);
                }
                uint32_t b0, b1, b2, b3;
                uint32_t baddr = bbase +
                    (uint32_t)((warp_n * 16 + lr + ((g >> 1) << 3)) * BS_STRIDE
                               + kk * 16 + ((g & 1) << 3)) * 2;
                LDSM4(b0, b1, b2, b3, baddr);
#pragma unroll
                for (int mt = 0; mt < 2; mt++) {
                    MMA16816(acc[mt][0], ah0[mt], ah1[mt], ah2[mt], ah3[mt], b0, b1);
                    MMA16816(acc[mt][1], ah0[mt], ah1[mt], ah2[mt], ah3[mt], b2, b3);
                    MMA16816(acc[mt][0], al0[mt], al1[mt], al2[mt], al3[mt], b0, b1);
                    MMA16816(acc[mt][1], al0[mt], al1[mt], al2[mt], al3[mt], b2, b3);
                }
            }
        } else {
            // c_lo chunk: pair with x_hi only
            int cc = c - 2;
#pragma unroll
            for (int kk = 0; kk < 4; kk++) {
                int kcol = cc * 64 + kk * 16;
                uint32_t ah0[2], ah1[2], ah2[2], ah3[2];
#pragma unroll
                for (int mt = 0; mt < 2; mt++) {
                    uint32_t abase = As_u +
                        (uint32_t)((warp_m * 32 + mt * 16 + lr + ((g & 1) << 3)) * AS_STRIDE
                                   + kcol + ((g >> 1) << 3)) * 2;
                    LDSM4(ah0[mt], ah1[mt], ah2[mt], ah3[mt], abase);
                }
                uint32_t b0, b1, b2, b3;
                uint32_t baddr = bbase +
                    (uint32_t)((warp_n * 16 + lr + ((g >> 1) << 3)) * BS_STRIDE
                               + kk * 16 + ((g & 1) << 3)) * 2;
                LDSM4(b0, b1, b2, b3, baddr);
#pragma unroll
                for (int mt = 0; mt < 2; mt++) {
                    MMA16816(acc[mt][0], ah0[mt], ah1[mt], ah2[mt], ah3[mt], b0, b1);
                    MMA16816(acc[mt][1], ah0[mt], ah1[mt], ah2[mt], ah3[mt], b2, b3);
                }
            }
        }

        if (c == VQ_CPT - 1) {
            int cb0 = warp_n * 16;
            int lcol = 2 * (lane & 3);
#pragma unroll
            for (int hf = 0; hf < 2; hf++) {
                int cloc = cb0 + hf * 8 + lcol;
                float cn0 = cns[cloc], cn1 = cns[cloc + 1];
                int code = t * 64 + cloc;
#pragma unroll
                for (int mt = 0; mt < 2; mt++)
#pragma unroll
                    for (int rs = 0; rs < 2; rs++) {
                        float dA = cn0 - 2.f * acc[mt][hf][rs * 2 + 0];
                        float dB = cn1 - 2.f * acc[mt][hf][rs * 2 + 1];
                        if (dA < d1v[mt][rs]) { d2v[mt][rs] = d1v[mt][rs]; d1v[mt][rs] = dA; j1v[mt][rs] = code; }
                        else if (dA < d2v[mt][rs]) d2v[mt][rs] = dA;
                        if (dB < d1v[mt][rs]) { d2v[mt][rs] = d1v[mt][rs]; d1v[mt][rs] = dB; j1v[mt][rs] = code + 1; }
                        else if (dB < d2v[mt][rs]) d2v[mt][rs] = dB;
                    }
            }
        }
    }

#pragma unroll
    for (int o = 1; o <= 2; o <<= 1) {
#pragma unroll
        for (int mt = 0; mt < 2; mt++)
#pragma unroll
            for (int rs = 0; rs < 2; rs++) {
                float od1 = __shfl_xor_sync(0xffffffffu, d1v[mt][rs], o);
                float od2 = __shfl_xor_sync(0xffffffffu, d2v[mt][rs], o);
                int   oj  = __shfl_xor_sync(0xffffffffu, j1v[mt][rs], o);
                if (od1 < d1v[mt][rs] || (od1 == d1v[mt][rs] && oj < j1v[mt][rs])) {
                    d2v[mt][rs] = fminf(d1v[mt][rs], od2);
                    d1v[mt][rs] = od1; j1v[mt][rs] = oj;
                } else {
                    d2v[mt][rs] = fminf(d2v[mt][rs], od1);
                }
            }
    }
    __syncthreads();
    if ((lane & 3) == 0) {
#pragma unroll
        for (int mt = 0; mt < 2; mt++)
#pragma unroll
            for (int rs = 0; rs < 2; rs++) {
                int nl = warp_m * 32 + mt * 16 + rs * 8 + (lane >> 2);
                rD1[nl * 4 + warp_n] = d1v[mt][rs];
                rD2[nl * 4 + warp_n] = d2v[mt][rs];
                rJ1[nl * 4 + warp_n] = j1v[mt][rs];
            }
    }
    __syncthreads();
    if (tid < 64) {
        float f1 = rD1[tid * 4], f2 = rD2[tid * 4];
        int fj = rJ1[tid * 4];
#pragma unroll
        for (int wn = 1; wn < 4; wn++) {
            float b1 = rD1[tid * 4 + wn], b2 = rD2[tid * 4 + wn];
            int bj = rJ1[tid * 4 + wn];
            if (b1 < f1 || (b1 == f1 && bj < fj)) {
                f2 = fminf(f1, b2); f1 = b1; fj = bj;
            } else {
                f2 = fminf(f2, b1);
            }
        }
        int node = node0 + tid;
        if (node < N_NODES) {
            outidx[node] = fj;
            if (f2 - f1 < VQ_MARGIN) {
                int p = atomicAdd(flagcnt, 1);
                flaglist[p] = node;
            }
        }
    }
}

// ---------------- exact fp32 rescue (order-invariant via atomicMin) --------
__global__ __launch_bounds__(128) void k_rescue(
        const float* __restrict__ h, const float* __restrict__ cb,
        const float* __restrict__ cnorm, const int* __restrict__ flaglist,
        const int* __restrict__ flagcnt, ull* __restrict__ best) {
    extern __shared__ __align__(16) float rs[];
    float* cs   = rs;
    float* hrow = cs + 128 * 128;
    float* rd   = hrow + 128;
    int*   rj   = (int*)(rd + 128);
    int tid = threadIdx.x;
    int c0 = blockIdx.x * 128;
    int code = c0 + tid;
#pragma unroll
    for (int it = 0; it < 32; it++) {
        int i = tid + it * 128;
        int row = i >> 5, c4 = i & 31;
        float4 v = make_float4(0.f, 0.f, 0.f, 0.f);
        if (c0 + row < CODEBOOK_N) v = __ldg(&((const float4*)cb)[(size_t)(c0 + row) * 32 + c4]);
        *(float4*)&cs[row * 128 + c4 * 4] = v;
    }
    float cn = cnorm[code];
    __syncthreads();
    int cnt = *flagcnt;
    const float4* crow4 = (const float4*)&cs[tid * 128];
    const float4* h4 = (const float4*)hrow;
    for (int f = 0; f < cnt; f++) {
        int node = flaglist[f];
        if (tid < 32) ((float4*)hrow)[tid] = ((const float4*)(h + (size_t)node * DIM))[tid];
        __syncthreads();
        float dot = 0.f;
#pragma unroll
        for (int k4 = 0; k4 < 32; k4++) {
            int i = (k4 + tid) & 31;
            float4 cv = crow4[i];
            float4 hv = h4[i];
            dot += cv.x * hv.x + cv.y * hv.y + cv.z * hv.z + cv.w * hv.w;
        }
        float d = cn - 2.f * dot;
        rd[tid] = d; rj[tid] = code;
        __syncthreads();
        for (int o = 64; o; o >>= 1) {
            if (tid < o) {
                float od = rd[tid + o]; int oc = rj[tid + o];
                if (od < rd[tid] || (od == rd[tid] && oc < rj[tid])) {
                    rd[tid] = od; rj[tid] = oc;
                }
            }
            __syncthreads();
        }
        if (tid == 0) {
            ull key = ((ull)fkey(rd[0]) << 32) | (uint32_t)rj[0];
            atomicMin(&best[node], key);
        }
        __syncthreads();
    }
}

__global__ void k_flagapply(const int* __restrict__ flaglist, const int* __restrict__ flagcnt,
                            const ull* __restrict__ best, int* __restrict__ outidx) {
    int cnt = *flagcnt;
    for (int i = blockIdx.x * blockDim.x + threadIdx.x; i < cnt; i += gridDim.x * blockDim.x) {
        int node = flaglist[i];
        outidx[node] = (int)(best[node] & 0xFFFFFFFFull);
    }
}

// ---------------- final per-node ----------------
__global__ void k_final(const float* __restrict__ h, const float* __restrict__ cb,
                        const int* __restrict__ idx, const float* __restrict__ score,
                        const int* __restrict__ batch, float* __restrict__ cacc,
                        float* __restrict__ sacc, float* __restrict__ cmt) {
    __shared__ float sh[256];
    int i = blockIdx.x * blockDim.x + threadIdx.x;
    float local = 0.f;
    if (i < N_NODES * DIM) {
        int node = i >> 7, d = i & 127;
        float hv = h[i];
        float q = cb[idx[node] * DIM + d];
        float diff = q - hv;
        local = diff * diff;
        float res = hv + q;
        float sc = score[node];
        int b = batch[node];
        atomicAdd(&cacc[b * DIM + d], res * sc);
        atomicAdd(&sacc[b * DIM + d], res * (1.f - sc));
    }
    sh[threadIdx.x] = local;
    __syncthreads();
    for (int o = 128; o; o >>= 1) {
        if (threadIdx.x < o) sh[threadIdx.x] += sh[threadIdx.x + o];
        __syncthreads();
    }
    if (threadIdx.x == 0) atomicAdd(cmt, sh[0]);
}

__global__ void k_cmtfin(const float* __restrict__ cmt, float* __restrict__ out) {
    out[2 * N_GRAPHS * DIM] = COMMIT_W * cmt[0] / (float)(N_NODES * DIM);
}

// ---------------- launcher ----------------
extern "C" void kernel_launch(void* const* d_in, const int* in_sizes, int n_in,
                              void* d_out, int out_size) {
    const float* x        = (const float*)d_in[0];
    const int*   ei       = (const int*)  d_in[1];
    const int*   batch    = (const int*)  d_in[2];
    const float* score    = (const float*)d_in[3];
    const float* cW1      = (const float*)d_in[4];
    const float* cb1      = (const float*)d_in[5];
    const float* cW2      = (const float*)d_in[6];
    const float* cb2      = (const float*)d_in[7];
    const float* bng      = (const float*)d_in[8];
    const float* bnb      = (const float*)d_in[9];
    const float* codebook = (const float*)d_in[10];
    const float* fc1W     = (const float*)d_in[11];
    const float* fc1b     = (const float*)d_in[12];
    const float* fc2W     = (const float*)d_in[13];
    const float* fc2b     = (const float*)d_in[14];
    float* out = (float*)d_out;
    const int* src = ei;
    const int* dst = ei + N_EDGES;

    void *p_z, *p_t1, *p_t2, *p_h, *p_deg, *p_offs, *p_cursor, *p_csrk;
    void *p_pstats, *p_mean, *p_invstd, *p_cnorm, *p_idx, *p_cacc, *p_sacc, *p_cmt;
    void *p_cbs, *p_flag, *p_fcnt, *p_best;
    cudaGetSymbolAddress(&p_z, g_z);
    cudaGetSymbolAddress(&p_t1, g_t1);
    cudaGetSymbolAddress(&p_t2, g_t2);
    cudaGetSymbolAddress(&p_h, g_h);
    cudaGetSymbolAddress(&p_deg, g_deg);
    cudaGetSymbolAddress(&p_offs, g_offs);
    cudaGetSymbolAddress(&p_cursor, g_cursor);
    cudaGetSymbolAddress(&p_csrk, g_csrk);
    cudaGetSymbolAddress(&p_pstats, g_pstats);
    cudaGetSymbolAddress(&p_mean, g_mean);
    cudaGetSymbolAddress(&p_invstd, g_invstd);
    cudaGetSymbolAddress(&p_cnorm, g_cnorm);
    cudaGetSymbolAddress(&p_idx, g_idx);
    cudaGetSymbolAddress(&p_cacc, g_cacc);
    cudaGetSymbolAddress(&p_sacc, g_sacc);
    cudaGetSymbolAddress(&p_cmt, g_cmt);
    cudaGetSymbolAddress(&p_cbs, g_cbs);
    cudaGetSymbolAddress(&p_flag, g_flaglist);
    cudaGetSymbolAddress(&p_fcnt, g_flagcnt);
    cudaGetSymbolAddress(&p_best, g_best);

    const int SMEM_VQ = 64 * AS_STRIDE * 2 + 4 * BS_BUF_H * 2 + 64 * 4 + 256 * 4 * 3;
    const int SMEM_RESCUE = 128 * 128 * 4 + 128 * 4 * 3;
    static bool attr_set = false;
    if (!attr_set) {
        cudaFuncSetAttribute(k_vq_mma, cudaFuncAttributeMaxDynamicSharedMemorySize, SMEM_VQ);
        cudaFuncSetAttribute(k_rescue, cudaFuncAttributeMaxDynamicSharedMemorySize, SMEM_RESCUE);
        attr_set = true;
    }

    // CSR build, canonicalized to exact EDGE order (matches reference segment_sum)
    cudaMemsetAsync(p_deg, 0, N_NODES * sizeof(int));
    k_hist<<<(N_EDGES + 255) / 256, 256>>>(dst, (int*)p_deg);
    k_scan<<<1, 1024>>>((const int*)p_deg, (int*)p_offs);
    cudaMemcpyAsync(p_cursor, p_offs, N_NODES * sizeof(int), cudaMemcpyDeviceToDevice);
    k_fill<<<(N_EDGES + 255) / 256, 256>>>(src, dst, (int*)p_cursor, (ull*)p_csrk);
    k_sortcsr<<<(N_NODES + 127) / 128, 128>>>((const int*)p_offs, (ull*)p_csrk);

    // codebook prep
    k_cnorm<<<(CODEBOOK_PAD * 32 + 255) / 256, 256>>>(codebook, (float*)p_cnorm);
    k_split_cb<<<(CODEBOOK_PAD * DIM + 255) / 256, 256>>>(codebook, (__half*)p_cbs);

    // MLP chain: fp32 (R4/R7-identical math), deterministic stats
    const int gemmBlocks = (N_NODES + 63) / 64;
    const float* h = x;
    for (int l = 0; l < N_LAYERS; l++) {
        k_agg<<<(N_NODES * 32 + 255) / 256, 256>>>(h, (const int*)p_offs,
                                                   (const ull*)p_csrk, (float*)p_z);
        k_gemm<<<gemmBlocks, 256>>>((const float*)p_z, cW1 + l * DIM * DIM, cb1 + l * DIM,
                                    (float*)p_t1, N_NODES, 1);
        k_gemm<<<gemmBlocks, 256>>>((const float*)p_t1, cW2 + l * DIM * DIM, cb2 + l * DIM,
                                    (float*)p_t2, N_NODES, 1);
        k_stats<<<STAT_BLOCKS, 256>>>((const float*)p_t2, (float*)p_pstats);
        k_bnfin<<<1, 128>>>((const float*)p_pstats, (float*)p_mean, (float*)p_invstd);
        k_bnapply<<<(N_NODES * DIM + 255) / 256, 256>>>(
            (const float*)p_t2, (const float*)p_mean, (const float*)p_invstd,
            bng + l * DIM, bnb + l * DIM, (float*)p_h);
        h = (const float*)p_h;
    }

    // VQ search (fp16 3-term tensor cores) + exact rescue
    cudaMemsetAsync(p_fcnt, 0, sizeof(int));
    cudaMemsetAsync(p_best, 0xFF, N_NODES * sizeof(ull));
    k_vq_mma<<<VQ_GRID, 256, SMEM_VQ>>>((const float*)p_h, (const __half*)p_cbs,
                                        (const float*)p_cnorm, (int*)p_idx,
                                        (int*)p_flag, (int*)p_fcnt);
    k_rescue<<<CODEBOOK_PAD / 128, 128, SMEM_RESCUE>>>(
        (const float*)p_h, codebook, (const float*)p_cnorm,
        (const int*)p_flag, (const int*)p_fcnt, (ull*)p_best);
    k_flagapply<<<40, 256>>>((const int*)p_flag, (const int*)p_fcnt,
                             (const ull*)p_best, (int*)p_idx);

    cudaMemsetAsync(p_cacc, 0, N_GRAPHS * DIM * sizeof(float));
    cudaMemsetAsync(p_sacc, 0, N_GRAPHS * DIM * sizeof(float));
    cudaMemsetAsync(p_cmt, 0, sizeof(float));
    k_final<<<(N_NODES * DIM + 255) / 256, 256>>>(
        (const float*)p_h, codebook, (const int*)p_idx, score, batch,
        (float*)p_cacc, (float*)p_sacc, (float*)p_cmt);

    k_gemm<<<(N_GRAPHS + 63) / 64, 256>>>((const float*)p_cacc, fc1W, fc1b,
                                          out, N_GRAPHS, 1);
    k_gemm<<<(N_GRAPHS + 63) / 64, 256>>>((const float*)p_sacc, fc2W, fc2b,
                                          out + N_GRAPHS * DIM, N_GRAPHS, 1);
    k_cmtfin<<<1, 1>>>((const float*)p_cmt, out);
}

// round 13
// speedup vs baseline: 1.8795x; 1.2228x over previous
#include <cuda_runtime.h>
#include <cuda_fp16.h>
#include <cstdint>
#include <math.h>

#define N_NODES   20000
#define N_EDGES   320000
#define DIM       128
#define CODEBOOK_N 12000
#define CODEBOOK_PAD 12032
#define N_GRAPHS  256
#define N_LAYERS  5
#define BN_EPS    1e-5f
#define COMMIT_W  0.25f
#define STAT_BLOCKS 157
#define NODE_PAD  20032            // 313*64

// VQ: exact fp16 3-term product via pass pairing (R8/R12 machinery),
// codebook split into VQ_SEGS segments for chip-level load balance.
#define VQ_K       256
#define VQ_TILES   188
#define VQ_CPT     4
#define VQ_SEGS    4
#define VQ_TPS     47              // tiles per segment (188/4)
#define VQ_CPS     (VQ_TPS*VQ_CPT) // chunks per segment = 188
#define VQ_MBLK    313             // ceil(20000/64)
#define VQ_MARGIN  0.02f
#define AS_STRIDE  264
#define BS_STRIDE  72
#define BS_BUF_H   (64*BS_STRIDE)

typedef unsigned long long ull;

// ---------------- scratch ----------------
__device__ float g_z [N_NODES*DIM];
__device__ float g_t1[N_NODES*DIM];
__device__ float g_t2[N_NODES*DIM];
__device__ float g_h [N_NODES*DIM];
__device__ int   g_deg[N_NODES];
__device__ int   g_offs[N_NODES+1];
__device__ int   g_cursor[N_NODES];
__device__ ull   g_csrk[N_EDGES];   // (edge_idx<<32)|src — sorted per node = edge order
__device__ float g_pstats[STAT_BLOCKS*2*DIM];
__device__ float g_mean[DIM];
__device__ float g_invstd[DIM];
__device__ float g_cnorm[CODEBOOK_PAD];
__device__ int   g_idx[N_NODES];
__device__ float g_cacc[N_GRAPHS*DIM];
__device__ float g_sacc[N_GRAPHS*DIM];
__device__ float g_cmt[1];
__device__ __half g_cbs[(size_t)CODEBOOK_PAD * VQ_K];
__device__ float g_pd1[VQ_SEGS*NODE_PAD];
__device__ float g_pd2[VQ_SEGS*NODE_PAD];
__device__ int   g_pj1[VQ_SEGS*NODE_PAD];
__device__ int   g_flaglist[N_NODES];
__device__ int   g_flagcnt[1];
__device__ ull   g_best[N_NODES];

// ---------------- asm helpers ----------------
__device__ __forceinline__ uint32_t smem_u32(const void* p) {
    uint32_t a;
    asm("{ .reg .u64 t; cvta.to.shared.u64 t, %1; cvt.u32.u64 %0, t; }" : "=r"(a) : "l"(p));
    return a;
}
#define CP_ASYNC16(dst, src) \
    asm volatile("cp.async.cg.shared.global [%0], [%1], 16;" :: "r"(dst), "l"(src) : "memory")
#define CP_COMMIT() asm volatile("cp.async.commit_group;" ::: "memory")
#define CP_WAIT(n)  asm volatile("cp.async.wait_group %0;" :: "n"(n) : "memory")
#define LDSM4(r0,r1,r2,r3,addr) \
    asm volatile("ldmatrix.sync.aligned.m8n8.x4.shared.b16 {%0,%1,%2,%3}, [%4];" \
        : "=r"(r0), "=r"(r1), "=r"(r2), "=r"(r3) : "r"(addr))
#define MMA16816(d, a0,a1,a2,a3, b0,b1) \
    asm volatile("mma.sync.aligned.m16n8k16.row.col.f32.f16.f16.f32 " \
        "{%0,%1,%2,%3}, {%4,%5,%6,%7}, {%8,%9}, {%0,%1,%2,%3};" \
        : "+f"((d)[0]), "+f"((d)[1]), "+f"((d)[2]), "+f"((d)[3]) \
        : "r"(a0), "r"(a1), "r"(a2), "r"(a3), "r"(b0), "r"(b1))

__device__ __forceinline__ uint32_t fkey(float f) {
    uint32_t u = __float_as_uint(f);
    return (u & 0x80000000u) ? ~u : (u | 0x80000000u);
}
__device__ __forceinline__ void split16(float f, __half& hi, __half& lo) {
    hi = __float2half_rn(f);
    lo = __float2half_rn(f - __half2float(hi));
}

// ---------------- CSR build: edge-order deterministic ----------------------
__global__ void k_hist(const int* __restrict__ dst, int* __restrict__ deg) {
    int e = blockIdx.x * blockDim.x + threadIdx.x;
    if (e < N_EDGES) atomicAdd(&deg[dst[e]], 1);
}
__global__ void k_scan(const int* __restrict__ deg, int* __restrict__ offs) {
    __shared__ int sh[1024];
    __shared__ int carry;
    int tid = threadIdx.x;
    if (tid == 0) { carry = 0; offs[0] = 0; }
    __syncthreads();
    for (int base = 0; base < N_NODES; base += 1024) {
        int v = (base + tid < N_NODES) ? deg[base + tid] : 0;
        sh[tid] = v;
        __syncthreads();
        for (int o = 1; o < 1024; o <<= 1) {
            int t = (tid >= o) ? sh[tid - o] : 0;
            __syncthreads();
            sh[tid] += t;
            __syncthreads();
        }
        if (base + tid < N_NODES) offs[base + tid + 1] = carry + sh[tid];
        __syncthreads();
        if (tid == 0) carry += sh[1023];
        __syncthreads();
    }
}
__global__ void k_fill(const int* __restrict__ src, const int* __restrict__ dst,
                       int* __restrict__ cursor, ull* __restrict__ csrk) {
    int e = blockIdx.x * blockDim.x + threadIdx.x;
    if (e < N_EDGES) {
        int d = dst[e];
        int slot = atomicAdd(&cursor[d], 1);
        csrk[slot] = ((ull)(uint32_t)e << 32) | (uint32_t)src[e];
    }
}
__global__ void k_sortcsr(const int* __restrict__ offs, ull* __restrict__ csrk) {
    int n = blockIdx.x * blockDim.x + threadIdx.x;
    if (n >= N_NODES) return;
    int s = offs[n], e = offs[n + 1];
    for (int i = s + 1; i < e; i++) {
        ull v = csrk[i];
        int j = i - 1;
        while (j >= s && csrk[j] > v) { csrk[j + 1] = csrk[j]; j--; }
        csrk[j + 1] = v;
    }
}

// ---------------- aggregation: fp32, edge order (FROZEN) ------------------
__global__ void k_agg(const float* __restrict__ h, const int* __restrict__ offs,
                      const ull* __restrict__ csrk, float* __restrict__ z) {
    int warp = (blockIdx.x * blockDim.x + threadIdx.x) >> 5;
    int lane = threadIdx.x & 31;
    if (warp >= N_NODES) return;
    const float4* hv = (const float4*)h;
    float4 acc = hv[warp * 32 + lane];
    int s = offs[warp], e = offs[warp + 1];
    for (int i = s; i < e; i++) {
        int sidx = (int)(uint32_t)(__ldg(&csrk[i]) & 0xFFFFFFFFull);
        float4 v = hv[sidx * 32 + lane];
        acc.x += v.x; acc.y += v.y; acc.z += v.z; acc.w += v.w;
    }
    ((float4*)z)[warp * 32 + lane] = acc;
}

// ---------------- GEMM fp32 (FROZEN) --------------------------------------
__global__ __launch_bounds__(256) void k_gemm(
        const float* __restrict__ A, const float* __restrict__ W,
        const float* __restrict__ bias, float* __restrict__ out,
        int M, int doRelu) {
    __shared__ float As[64][32];
    __shared__ float Ws[32][128];
    int tid = threadIdx.x;
    int tx = tid & 31, ty = tid >> 5;
    int row0 = blockIdx.x * 64;
    float acc[8][4];
#pragma unroll
    for (int r = 0; r < 8; r++)
#pragma unroll
        for (int c = 0; c < 4; c++) acc[r][c] = 0.f;

    for (int kt = 0; kt < DIM; kt += 32) {
#pragma unroll
        for (int it = 0; it < 2; it++) {
            int i = tid + it * 256;
            int r = i >> 3, c4 = i & 7;
            int row = row0 + r;
            float4 v = make_float4(0.f, 0.f, 0.f, 0.f);
            if (row < M) v = *(const float4*)&A[row * DIM + kt + c4 * 4];
            *(float4*)&As[r][c4 * 4] = v;
        }
#pragma unroll
        for (int it = 0; it < 4; it++) {
            int i = tid + it * 256;
            int r = i >> 5, c4 = i & 31;
            *(float4*)&Ws[r][c4 * 4] = *(const float4*)&W[(kt + r) * DIM + c4 * 4];
        }
        __syncthreads();
#pragma unroll
        for (int k = 0; k < 32; k++) {
            float4 w = *(float4*)&Ws[k][tx * 4];
#pragma unroll
            for (int r = 0; r < 8; r++) {
                float a = As[ty * 8 + r][k];
                acc[r][0] += a * w.x;
                acc[r][1] += a * w.y;
                acc[r][2] += a * w.z;
                acc[r][3] += a * w.w;
            }
        }
        __syncthreads();
    }
    float4 b = *(const float4*)&bias[tx * 4];
#pragma unroll
    for (int r = 0; r < 8; r++) {
        int row = row0 + ty * 8 + r;
        if (row < M) {
            float v0 = acc[r][0] + b.x;
            float v1 = acc[r][1] + b.y;
            float v2 = acc[r][2] + b.z;
            float v3 = acc[r][3] + b.w;
            if (doRelu) {
                v0 = fmaxf(v0, 0.f); v1 = fmaxf(v1, 0.f);
                v2 = fmaxf(v2, 0.f); v3 = fmaxf(v3, 0.f);
            }
            *(float4*)&out[row * DIM + tx * 4] = make_float4(v0, v1, v2, v3);
        }
    }
}

// ---------------- BN stats (FROZEN) ---------------------------------------
__global__ void k_stats(const float* __restrict__ t2, float* __restrict__ pstats) {
    __shared__ float ss[256], qq[256];
    int tid = threadIdx.x;
    int col = tid & 127, half = tid >> 7;
    float s = 0.f, q = 0.f;
    int row0 = blockIdx.x * 128;
    for (int i = half; i < 128; i += 2) {
        int r = row0 + i;
        if (r < N_NODES) {
            float v = t2[(size_t)r * DIM + col];
            s += v; q += v * v;
        }
    }
    ss[tid] = s; qq[tid] = q;
    __syncthreads();
    if (tid < 128) {
        pstats[blockIdx.x * 256 + tid]       = ss[tid] + ss[tid + 128];
        pstats[blockIdx.x * 256 + 128 + tid] = qq[tid] + qq[tid + 128];
    }
}

__global__ void k_bnfin(const float* __restrict__ pstats,
                        float* __restrict__ mean, float* __restrict__ invstd) {
    int d = threadIdx.x;
    float s = 0.f, q = 0.f;
    for (int b = 0; b < STAT_BLOCKS; b++) {
        s += pstats[b * 256 + d];
        q += pstats[b * 256 + 128 + d];
    }
    float mu = s / (float)N_NODES;
    float var = q / (float)N_NODES - mu * mu;
    mean[d] = mu;
    invstd[d] = rsqrtf(var + BN_EPS);
}

__global__ void k_bnapply(const float* __restrict__ z, const float* __restrict__ mean,
                          const float* __restrict__ invstd, const float* __restrict__ gamma,
                          const float* __restrict__ beta, float* __restrict__ h) {
    int i = blockIdx.x * blockDim.x + threadIdx.x;
    if (i < N_NODES * DIM) {
        int d = i & (DIM - 1);
        h[i] = (z[i] - mean[d]) * invstd[d] * gamma[d] + beta[d];
    }
}

// ---------------- VQ: codebook norms ----------------
__global__ void k_cnorm(const float* __restrict__ cb, float* __restrict__ cnorm) {
    int warp = (blockIdx.x * blockDim.x + threadIdx.x) >> 5;
    int lane = threadIdx.x & 31;
    if (warp >= CODEBOOK_PAD) return;
    if (warp >= CODEBOOK_N) { if (lane == 0) cnorm[warp] = 1e30f; return; }
    float4 v = ((const float4*)cb)[warp * 32 + lane];
    float s = v.x * v.x + v.y * v.y + v.z * v.z + v.w * v.w;
#pragma unroll
    for (int o = 16; o; o >>= 1) s += __shfl_xor_sync(0xffffffffu, s, o);
    if (lane == 0) cnorm[warp] = s;
}

// ---------------- split codebook: [c_hi | c_lo] fp16, K=256 ----------------
__global__ void k_split_cb(const float* __restrict__ cb, __half* __restrict__ cbs) {
    int gid = blockIdx.x * blockDim.x + threadIdx.x;
    if (gid >= CODEBOOK_PAD * DIM) return;
    int j = gid >> 7, d = gid & 127;
    float v = (j < CODEBOOK_N) ? cb[j * DIM + d] : 0.f;
    __half hi, lo; split16(v, hi, lo);
    __half* row = cbs + (size_t)j * VQ_K;
    row[d] = hi;
    row[128 + d] = lo;
}

// ---------------- VQ main: segment-split fp16 3-term GEMM-argmin -----------
// grid (313, 4): blockIdx.x = M-tile (64 nodes), blockIdx.y = codebook segment
// (47 tiles = 3008 codes). Emits per-seg (d1,d2,j1); merged deterministically.
__global__ __launch_bounds__(256, 2) void k_vq_mma(
        const float* __restrict__ h, const __half* __restrict__ cbs,
        const float* __restrict__ cnorm,
        float* __restrict__ pd1, float* __restrict__ pd2, int* __restrict__ pj1) {
    extern __shared__ __align__(16) char dyn[];
    __half* As = (__half*)dyn;                 // [64][264]
    __half* Bs = As + 64 * AS_STRIDE;          // [4][64][72]
    float* cns = (float*)(Bs + 4 * BS_BUF_H);  // [64]
    float* rD1 = cns + 64;                     // [64][4]
    float* rD2 = rD1 + 256;
    int*   rJ1 = (int*)(rD2 + 256);
    uint32_t As_u = smem_u32(As);
    uint32_t Bs_u = smem_u32(Bs);

    int tid = threadIdx.x, lane = tid & 31, wid = tid >> 5;
    int warp_m = wid & 1, warp_n = wid >> 1;   // 2m x 4n
    int node0 = blockIdx.x * 64;
    int seg = blockIdx.y;
    int cstart = seg * VQ_CPS;                 // multiple of 4 -> ring starts at buf 0
    int cend = cstart + VQ_CPS;

    // ---- A: [x_hi | x_lo]; 4 threads/row ----
    {
        int r = tid >> 2, q = tid & 3;
        bool valid = (node0 + r) < N_NODES;
        const float4* hp = (const float4*)(h + (size_t)(valid ? node0 + r : 0) * DIM);
        __half* arow = As + r * AS_STRIDE;
#pragma unroll
        for (int v = 0; v < 8; v++) {
            float4 f = valid ? hp[q * 8 + v] : make_float4(0.f, 0.f, 0.f, 0.f);
            __half hx, lx, hy, ly, hz, lz, hw, lw;
            split16(f.x, hx, lx); split16(f.y, hy, ly);
            split16(f.z, hz, lz); split16(f.w, hw, lw);
            int col = q * 32 + v * 4;
            arow[col + 0] = hx; arow[col + 1] = hy; arow[col + 2] = hz; arow[col + 3] = hw;
            arow[128 + col + 0] = lx; arow[128 + col + 1] = ly;
            arow[128 + col + 2] = lz; arow[128 + col + 3] = lw;
        }
    }

    // ---- preload first two chunks of this segment ----
#pragma unroll
    for (int pc = 0; pc < 2; pc++) {
        int ci = cstart + pc;
        const __half* base = cbs + (size_t)(ci >> 2) * 64 * VQ_K + (ci & 3) * 64;
#pragma unroll
        for (int it = 0; it < 2; it++) {
            int i = tid + it * 256;
            int row = i >> 3, c16 = i & 7;
            CP_ASYNC16(Bs_u + (uint32_t)(pc * BS_BUF_H + row * BS_STRIDE + c16 * 8) * 2,
                       base + (size_t)row * VQ_K + c16 * 8);
        }
        CP_COMMIT();
    }

    float d1v[2][2] = {{1e38f, 1e38f}, {1e38f, 1e38f}};
    float d2v[2][2] = {{1e38f, 1e38f}, {1e38f, 1e38f}};
    int   j1v[2][2] = {{0, 0}, {0, 0}};
    int lr = lane & 7, g = lane >> 3;
    float acc[2][2][4];

    for (int ci = cstart; ci < cend; ci++) {
        int t = ci >> 2, c = ci & 3;
        int buf = ci & 3;
        if (c == 0) {
#pragma unroll
            for (int mt = 0; mt < 2; mt++)
#pragma unroll
                for (int hf = 0; hf < 2; hf++)
#pragma unroll
                    for (int r = 0; r < 4; r++) acc[mt][hf][r] = 0.f;
        }
        if (ci + 2 < cend) {
            int pidx = ci + 2;
            int pbuf = pidx & 3;
            const __half* base = cbs + (size_t)(pidx >> 2) * 64 * VQ_K + (pidx & 3) * 64;
#pragma unroll
            for (int it = 0; it < 2; it++) {
                int i = tid + it * 256;
                int row = i >> 3, c16 = i & 7;
                CP_ASYNC16(Bs_u + (uint32_t)(pbuf * BS_BUF_H + row * BS_STRIDE + c16 * 8) * 2,
                           base + (size_t)row * VQ_K + c16 * 8);
            }
            CP_COMMIT();
            CP_WAIT(2);
        } else {
            CP_WAIT(0);
        }
        __syncthreads();
        if (c == 0 && tid < 64) cns[tid] = __ldg(&cnorm[t * 64 + tid]);

        uint32_t bbase = Bs_u + (uint32_t)(buf * BS_BUF_H) * 2;
        if (c < 2) {
            // c_hi chunk: pair with x_hi AND x_lo
#pragma unroll
            for (int kk = 0; kk < 4; kk++) {
                int kcol = c * 64 + kk * 16;
                uint32_t ah0[2], ah1[2], ah2[2], ah3[2];
                uint32_t al0[2], al1[2], al2[2], al3[2];
#pragma unroll
                for (int mt = 0; mt < 2; mt++) {
                    uint32_t abase = As_u +
                        (uint32_t)((warp_m * 32 + mt * 16 + lr + ((g & 1) << 3)) * AS_STRIDE
                                   + kcol + ((g >> 1) << 3)) * 2;
                    LDSM4(ah0[mt], ah1[mt], ah2[mt], ah3[mt], abase);
                    LDSM4(al0[mt], al1[mt], al2[mt], al3[mt], abase + 128 * 2);
                }
                uint32_t b0, b1, b2, b3;
                uint32_t baddr = bbase +
                    (uint32_t)((warp_n * 16 + lr + ((g >> 1) << 3)) * BS_STRIDE
                               + kk * 16 + ((g & 1) << 3)) * 2;
                LDSM4(b0, b1, b2, b3, baddr);
#pragma unroll
                for (int mt = 0; mt < 2; mt++) {
                    MMA16816(acc[mt][0], ah0[mt], ah1[mt], ah2[mt], ah3[mt], b0, b1);
                    MMA16816(acc[mt][1], ah0[mt], ah1[mt], ah2[mt], ah3[mt], b2, b3);
                    MMA16816(acc[mt][0], al0[mt], al1[mt], al2[mt], al3[mt], b0, b1);
                    MMA16816(acc[mt][1], al0[mt], al1[mt], al2[mt], al3[mt], b2, b3);
                }
            }
        } else {
            // c_lo chunk: pair with x_hi only
            int cc = c - 2;
#pragma unroll
            for (int kk = 0; kk < 4; kk++) {
                int kcol = cc * 64 + kk * 16;
                uint32_t ah0[2], ah1[2], ah2[2], ah3[2];
#pragma unroll
                for (int mt = 0; mt < 2; mt++) {
                    uint32_t abase = As_u +
                        (uint32_t)((warp_m * 32 + mt * 16 + lr + ((g & 1) << 3)) * AS_STRIDE
                                   + kcol + ((g >> 1) << 3)) * 2;
                    LDSM4(ah0[mt], ah1[mt], ah2[mt], ah3[mt], abase);
                }
                uint32_t b0, b1, b2, b3;
                uint32_t baddr = bbase +
                    (uint32_t)((warp_n * 16 + lr + ((g >> 1) << 3)) * BS_STRIDE
                               + kk * 16 + ((g & 1) << 3)) * 2;
                LDSM4(b0, b1, b2, b3, baddr);
#pragma unroll
                for (int mt = 0; mt < 2; mt++) {
                    MMA16816(acc[mt][0], ah0[mt], ah1[mt], ah2[mt], ah3[mt], b0, b1);
                    MMA16816(acc[mt][1], ah0[mt], ah1[mt], ah2[mt], ah3[mt], b2, b3);
                }
            }
        }

        if (c == VQ_CPT - 1) {
            int cb0 = warp_n * 16;
            int lcol = 2 * (lane & 3);
#pragma unroll
            for (int hf = 0; hf < 2; hf++) {
                int cloc = cb0 + hf * 8 + lcol;
                float cn0 = cns[cloc], cn1 = cns[cloc + 1];
                int code = t * 64 + cloc;
#pragma unroll
                for (int mt = 0; mt < 2; mt++)
#pragma unroll
                    for (int rs = 0; rs < 2; rs++) {
                        float dA = cn0 - 2.f * acc[mt][hf][rs * 2 + 0];
                        float dB = cn1 - 2.f * acc[mt][hf][rs * 2 + 1];
                        if (dA < d1v[mt][rs]) { d2v[mt][rs] = d1v[mt][rs]; d1v[mt][rs] = dA; j1v[mt][rs] = code; }
                        else if (dA < d2v[mt][rs]) d2v[mt][rs] = dA;
                        if (dB < d1v[mt][rs]) { d2v[mt][rs] = d1v[mt][rs]; d1v[mt][rs] = dB; j1v[mt][rs] = code + 1; }
                        else if (dB < d2v[mt][rs]) d2v[mt][rs] = dB;
                    }
            }
        }
    }

#pragma unroll
    for (int o = 1; o <= 2; o <<= 1) {
#pragma unroll
        for (int mt = 0; mt < 2; mt++)
#pragma unroll
            for (int rs = 0; rs < 2; rs++) {
                float od1 = __shfl_xor_sync(0xffffffffu, d1v[mt][rs], o);
                float od2 = __shfl_xor_sync(0xffffffffu, d2v[mt][rs], o);
                int   oj  = __shfl_xor_sync(0xffffffffu, j1v[mt][rs], o);
                if (od1 < d1v[mt][rs] || (od1 == d1v[mt][rs] && oj < j1v[mt][rs])) {
                    d2v[mt][rs] = fminf(d1v[mt][rs], od2);
                    d1v[mt][rs] = od1; j1v[mt][rs] = oj;
                } else {
                    d2v[mt][rs] = fminf(d2v[mt][rs], od1);
                }
            }
    }
    __syncthreads();
    if ((lane & 3) == 0) {
#pragma unroll
        for (int mt = 0; mt < 2; mt++)
#pragma unroll
            for (int rs = 0; rs < 2; rs++) {
                int nl = warp_m * 32 + mt * 16 + rs * 8 + (lane >> 2);
                rD1[nl * 4 + warp_n] = d1v[mt][rs];
                rD2[nl * 4 + warp_n] = d2v[mt][rs];
                rJ1[nl * 4 + warp_n] = j1v[mt][rs];
            }
    }
    __syncthreads();
    if (tid < 64) {
        float f1 = rD1[tid * 4], f2 = rD2[tid * 4];
        int fj = rJ1[tid * 4];
#pragma unroll
        for (int wn = 1; wn < 4; wn++) {
            float b1 = rD1[tid * 4 + wn], b2 = rD2[tid * 4 + wn];
            int bj = rJ1[tid * 4 + wn];
            if (b1 < f1 || (b1 == f1 && bj < fj)) {
                f2 = fminf(f1, b2); f1 = b1; fj = bj;
            } else {
                f2 = fminf(f2, b1);
            }
        }
        int slot = seg * NODE_PAD + node0 + tid;
        pd1[slot] = f1; pd2[slot] = f2; pj1[slot] = fj;
    }
}

// ---------------- merge segments (deterministic, fixed order) --------------
__global__ void k_vqmerge(const float* __restrict__ pd1, const float* __restrict__ pd2,
                          const int* __restrict__ pj1, int* __restrict__ outidx,
                          int* __restrict__ flaglist, int* __restrict__ flagcnt) {
    int n = blockIdx.x * blockDim.x + threadIdx.x;
    if (n >= N_NODES) return;
    float f1 = pd1[n], f2 = pd2[n];
    int fj = pj1[n];
#pragma unroll
    for (int s = 1; s < VQ_SEGS; s++) {
        float b1 = pd1[s * NODE_PAD + n], b2 = pd2[s * NODE_PAD + n];
        int bj = pj1[s * NODE_PAD + n];
        if (b1 < f1 || (b1 == f1 && bj < fj)) {
            f2 = fminf(f1, b2); f1 = b1; fj = bj;
        } else {
            f2 = fminf(f2, b1);
        }
    }
    outidx[n] = fj;
    if (f2 - f1 < VQ_MARGIN) {
        int p = atomicAdd(flagcnt, 1);
        flaglist[p] = n;
    }
}

// ---------------- exact fp32 rescue (order-invariant via atomicMin) --------
__global__ __launch_bounds__(128) void k_rescue(
        const float* __restrict__ h, const float* __restrict__ cb,
        const float* __restrict__ cnorm, const int* __restrict__ flaglist,
        const int* __restrict__ flagcnt, ull* __restrict__ best) {
    extern __shared__ __align__(16) float rs[];
    float* cs   = rs;
    float* hrow = cs + 128 * 128;
    float* rd   = hrow + 128;
    int*   rj   = (int*)(rd + 128);
    int tid = threadIdx.x;
    int c0 = blockIdx.x * 128;
    int code = c0 + tid;
#pragma unroll
    for (int it = 0; it < 32; it++) {
        int i = tid + it * 128;
        int row = i >> 5, c4 = i & 31;
        float4 v = make_float4(0.f, 0.f, 0.f, 0.f);
        if (c0 + row < CODEBOOK_N) v = __ldg(&((const float4*)cb)[(size_t)(c0 + row) * 32 + c4]);
        *(float4*)&cs[row * 128 + c4 * 4] = v;
    }
    float cn = cnorm[code];
    __syncthreads();
    int cnt = *flagcnt;
    const float4* crow4 = (const float4*)&cs[tid * 128];
    const float4* h4 = (const float4*)hrow;
    for (int f = 0; f < cnt; f++) {
        int node = flaglist[f];
        if (tid < 32) ((float4*)hrow)[tid] = ((const float4*)(h + (size_t)node * DIM))[tid];
        __syncthreads();
        float dot = 0.f;
#pragma unroll
        for (int k4 = 0; k4 < 32; k4++) {
            int i = (k4 + tid) & 31;
            float4 cv = crow4[i];
            float4 hv = h4[i];
            dot += cv.x * hv.x + cv.y * hv.y + cv.z * hv.z + cv.w * hv.w;
        }
        float d = cn - 2.f * dot;
        rd[tid] = d; rj[tid] = code;
        __syncthreads();
        for (int o = 64; o; o >>= 1) {
            if (tid < o) {
                float od = rd[tid + o]; int oc = rj[tid + o];
                if (od < rd[tid] || (od == rd[tid] && oc < rj[tid])) {
                    rd[tid] = od; rj[tid] = oc;
                }
            }
            __syncthreads();
        }
        if (tid == 0) {
            ull key = ((ull)fkey(rd[0]) << 32) | (uint32_t)rj[0];
            atomicMin(&best[node], key);
        }
        __syncthreads();
    }
}

__global__ void k_flagapply(const int* __restrict__ flaglist, const int* __restrict__ flagcnt,
                            const ull* __restrict__ best, int* __restrict__ outidx) {
    int cnt = *flagcnt;
    for (int i = blockIdx.x * blockDim.x + threadIdx.x; i < cnt; i += gridDim.x * blockDim.x) {
        int node = flaglist[i];
        outidx[node] = (int)(best[node] & 0xFFFFFFFFull);
    }
}

// ---------------- final per-node ----------------
__global__ void k_final(const float* __restrict__ h, const float* __restrict__ cb,
                        const int* __restrict__ idx, const float* __restrict__ score,
                        const int* __restrict__ batch, float* __restrict__ cacc,
                        float* __restrict__ sacc, float* __restrict__ cmt) {
    __shared__ float sh[256];
    int i = blockIdx.x * blockDim.x + threadIdx.x;
    float local = 0.f;
    if (i < N_NODES * DIM) {
        int node = i >> 7, d = i & 127;
        float hv = h[i];
        float q = cb[idx[node] * DIM + d];
        float diff = q - hv;
        local = diff * diff;
        float res = hv + q;
        float sc = score[node];
        int b = batch[node];
        atomicAdd(&cacc[b * DIM + d], res * sc);
        atomicAdd(&sacc[b * DIM + d], res * (1.f - sc));
    }
    sh[threadIdx.x] = local;
    __syncthreads();
    for (int o = 128; o; o >>= 1) {
        if (threadIdx.x < o) sh[threadIdx.x] += sh[threadIdx.x + o];
        __syncthreads();
    }
    if (threadIdx.x == 0) atomicAdd(cmt, sh[0]);
}

__global__ void k_cmtfin(const float* __restrict__ cmt, float* __restrict__ out) {
    out[2 * N_GRAPHS * DIM] = COMMIT_W * cmt[0] / (float)(N_NODES * DIM);
}

// ---------------- launcher ----------------
extern "C" void kernel_launch(void* const* d_in, const int* in_sizes, int n_in,
                              void* d_out, int out_size) {
    const float* x        = (const float*)d_in[0];
    const int*   ei       = (const int*)  d_in[1];
    const int*   batch    = (const int*)  d_in[2];
    const float* score    = (const float*)d_in[3];
    const float* cW1      = (const float*)d_in[4];
    const float* cb1      = (const float*)d_in[5];
    const float* cW2      = (const float*)d_in[6];
    const float* cb2      = (const float*)d_in[7];
    const float* bng      = (const float*)d_in[8];
    const float* bnb      = (const float*)d_in[9];
    const float* codebook = (const float*)d_in[10];
    const float* fc1W     = (const float*)d_in[11];
    const float* fc1b     = (const float*)d_in[12];
    const float* fc2W     = (const float*)d_in[13];
    const float* fc2b     = (const float*)d_in[14];
    float* out = (float*)d_out;
    const int* src = ei;
    const int* dst = ei + N_EDGES;

    void *p_z, *p_t1, *p_t2, *p_h, *p_deg, *p_offs, *p_cursor, *p_csrk;
    void *p_pstats, *p_mean, *p_invstd, *p_cnorm, *p_idx, *p_cacc, *p_sacc, *p_cmt;
    void *p_cbs, *p_pd1, *p_pd2, *p_pj1, *p_flag, *p_fcnt, *p_best;
    cudaGetSymbolAddress(&p_z, g_z);
    cudaGetSymbolAddress(&p_t1, g_t1);
    cudaGetSymbolAddress(&p_t2, g_t2);
    cudaGetSymbolAddress(&p_h, g_h);
    cudaGetSymbolAddress(&p_deg, g_deg);
    cudaGetSymbolAddress(&p_offs, g_offs);
    cudaGetSymbolAddress(&p_cursor, g_cursor);
    cudaGetSymbolAddress(&p_csrk, g_csrk);
    cudaGetSymbolAddress(&p_pstats, g_pstats);
    cudaGetSymbolAddress(&p_mean, g_mean);
    cudaGetSymbolAddress(&p_invstd, g_invstd);
    cudaGetSymbolAddress(&p_cnorm, g_cnorm);
    cudaGetSymbolAddress(&p_idx, g_idx);
    cudaGetSymbolAddress(&p_cacc, g_cacc);
    cudaGetSymbolAddress(&p_sacc, g_sacc);
    cudaGetSymbolAddress(&p_cmt, g_cmt);
    cudaGetSymbolAddress(&p_cbs, g_cbs);
    cudaGetSymbolAddress(&p_pd1, g_pd1);
    cudaGetSymbolAddress(&p_pd2, g_pd2);
    cudaGetSymbolAddress(&p_pj1, g_pj1);
    cudaGetSymbolAddress(&p_flag, g_flaglist);
    cudaGetSymbolAddress(&p_fcnt, g_flagcnt);
    cudaGetSymbolAddress(&p_best, g_best);

    const int SMEM_VQ = 64 * AS_STRIDE * 2 + 4 * BS_BUF_H * 2 + 64 * 4 + 256 * 4 * 3;
    const int SMEM_RESCUE = 128 * 128 * 4 + 128 * 4 * 3;
    static bool attr_set = false;
    if (!attr_set) {
        cudaFuncSetAttribute(k_vq_mma, cudaFuncAttributeMaxDynamicSharedMemorySize, SMEM_VQ);
        cudaFuncSetAttribute(k_rescue, cudaFuncAttributeMaxDynamicSharedMemorySize, SMEM_RESCUE);
        attr_set = true;
    }

    // CSR build, canonicalized to exact EDGE order (matches reference segment_sum)
    cudaMemsetAsync(p_deg, 0, N_NODES * sizeof(int));
    k_hist<<<(N_EDGES + 255) / 256, 256>>>(dst, (int*)p_deg);
    k_scan<<<1, 1024>>>((const int*)p_deg, (int*)p_offs);
    cudaMemcpyAsync(p_cursor, p_offs, N_NODES * sizeof(int), cudaMemcpyDeviceToDevice);
    k_fill<<<(N_EDGES + 255) / 256, 256>>>(src, dst, (int*)p_cursor, (ull*)p_csrk);
    k_sortcsr<<<(N_NODES + 127) / 128, 128>>>((const int*)p_offs, (ull*)p_csrk);

    // codebook prep
    k_cnorm<<<(CODEBOOK_PAD * 32 + 255) / 256, 256>>>(codebook, (float*)p_cnorm);
    k_split_cb<<<(CODEBOOK_PAD * DIM + 255) / 256, 256>>>(codebook, (__half*)p_cbs);

    // MLP chain: FROZEN fp32 pipeline (h must match R12 bit-for-bit)
    const int gemmBlocks = (N_NODES + 63) / 64;
    const float* h = x;
    for (int l = 0; l < N_LAYERS; l++) {
        k_agg<<<(N_NODES * 32 + 255) / 256, 256>>>(h, (const int*)p_offs,
                                                   (const ull*)p_csrk, (float*)p_z);
        k_gemm<<<gemmBlocks, 256>>>((const float*)p_z, cW1 + l * DIM * DIM, cb1 + l * DIM,
                                    (float*)p_t1, N_NODES, 1);
        k_gemm<<<gemmBlocks, 256>>>((const float*)p_t1, cW2 + l * DIM * DIM, cb2 + l * DIM,
                                    (float*)p_t2, N_NODES, 1);
        k_stats<<<STAT_BLOCKS, 256>>>((const float*)p_t2, (float*)p_pstats);
        k_bnfin<<<1, 128>>>((const float*)p_pstats, (float*)p_mean, (float*)p_invstd);
        k_bnapply<<<(N_NODES * DIM + 255) / 256, 256>>>(
            (const float*)p_t2, (const float*)p_mean, (const float*)p_invstd,
            bng + l * DIM, bnb + l * DIM, (float*)p_h);
        h = (const float*)p_h;
    }

    // VQ: segment-split tensor-core search + deterministic merge + exact rescue
    cudaMemsetAsync(p_fcnt, 0, sizeof(int));
    cudaMemsetAsync(p_best, 0xFF, N_NODES * sizeof(ull));
    k_vq_mma<<<dim3(VQ_MBLK, VQ_SEGS), 256, SMEM_VQ>>>(
        (const float*)p_h, (const __half*)p_cbs, (const float*)p_cnorm,
        (float*)p_pd1, (float*)p_pd2, (int*)p_pj1);
    k_vqmerge<<<(N_NODES + 255) / 256, 256>>>(
        (const float*)p_pd1, (const float*)p_pd2, (const int*)p_pj1,
        (int*)p_idx, (int*)p_flag, (int*)p_fcnt);
    k_rescue<<<CODEBOOK_PAD / 128, 128, SMEM_RESCUE>>>(
        (const float*)p_h, codebook, (const float*)p_cnorm,
        (const int*)p_flag, (const int*)p_fcnt, (ull*)p_best);
    k_flagapply<<<40, 256>>>((const int*)p_flag, (const int*)p_fcnt,
                             (const ull*)p_best, (int*)p_idx);

    cudaMemsetAsync(p_cacc, 0, N_GRAPHS * DIM * sizeof(float));
    cudaMemsetAsync(p_sacc, 0, N_GRAPHS * DIM * sizeof(float));
    cudaMemsetAsync(p_cmt, 0, sizeof(float));
    k_final<<<(N_NODES * DIM + 255) / 256, 256>>>(
        (const float*)p_h, codebook, (const int*)p_idx, score, batch,
        (float*)p_cacc, (float*)p_sacc, (float*)p_cmt);

    k_gemm<<<(N_GRAPHS + 63) / 64, 256>>>((const float*)p_cacc, fc1W, fc1b,
                                          out, N_GRAPHS, 1);
    k_gemm<<<(N_GRAPHS + 63) / 64, 256>>>((const float*)p_sacc, fc2W, fc2b,
                                          out + N_GRAPHS * DIM, N_GRAPHS, 1);
    k_cmtfin<<<1, 1>>>((const float*)p_cmt, out);
}

// round 14
// speedup vs baseline: 1.9108x; 1.0167x over previous
#include <cuda_runtime.h>
#include <cuda_fp16.h>
#include <cstdint>
#include <math.h>

#define N_NODES   20000
#define N_EDGES   320000
#define DIM       128
#define CODEBOOK_N 12000
#define CODEBOOK_PAD 12032
#define N_GRAPHS  256
#define N_LAYERS  5
#define BN_EPS    1e-5f
#define COMMIT_W  0.25f
#define STAT_BLOCKS 157
#define NODE_PAD  20032            // 313*64

// VQ: exact fp16 3-term product via pass pairing, 4-way codebook split.
#define VQ_K       256
#define VQ_TILES   188
#define VQ_CPT     4
#define VQ_SEGS    4
#define VQ_TPS     47
#define VQ_CPS     (VQ_TPS*VQ_CPT)
#define VQ_MBLK    313
#define VQ_MARGIN  0.02f
#define AS_STRIDE  264
#define BS_STRIDE  72
#define BS_BUF_H   (64*BS_STRIDE)

typedef unsigned long long ull;

// ---------------- scratch ----------------
__device__ float g_z [N_NODES*DIM];
__device__ float g_t2[N_NODES*DIM];
__device__ float g_h [N_NODES*DIM];
__device__ int   g_deg[N_NODES];
__device__ int   g_offs[N_NODES+1];
__device__ int   g_cursor[N_NODES];
__device__ ull   g_csrk[N_EDGES];   // (edge_idx<<32)|src — sorted per node = edge order
__device__ float g_pstats[STAT_BLOCKS*2*DIM];
__device__ float g_mean[DIM];
__device__ float g_invstd[DIM];
__device__ float g_cnorm[CODEBOOK_PAD];
__device__ int   g_idx[N_NODES];
__device__ float g_cacc[N_GRAPHS*DIM];
__device__ float g_sacc[N_GRAPHS*DIM];
__device__ float g_cmt[1];
__device__ __half g_cbs[(size_t)CODEBOOK_PAD * VQ_K];
__device__ float g_pd1[VQ_SEGS*NODE_PAD];
__device__ float g_pd2[VQ_SEGS*NODE_PAD];
__device__ int   g_pj1[VQ_SEGS*NODE_PAD];
__device__ int   g_flaglist[N_NODES];
__device__ int   g_flagcnt[1];
__device__ ull   g_best[N_NODES];

// ---------------- asm helpers ----------------
__device__ __forceinline__ uint32_t smem_u32(const void* p) {
    uint32_t a;
    asm("{ .reg .u64 t; cvta.to.shared.u64 t, %1; cvt.u32.u64 %0, t; }" : "=r"(a) : "l"(p));
    return a;
}
#define CP_ASYNC16(dst, src) \
    asm volatile("cp.async.cg.shared.global [%0], [%1], 16;" :: "r"(dst), "l"(src) : "memory")
#define CP_COMMIT() asm volatile("cp.async.commit_group;" ::: "memory")
#define CP_WAIT(n)  asm volatile("cp.async.wait_group %0;" :: "n"(n) : "memory")
#define LDSM4(r0,r1,r2,r3,addr) \
    asm volatile("ldmatrix.sync.aligned.m8n8.x4.shared.b16 {%0,%1,%2,%3}, [%4];" \
        : "=r"(r0), "=r"(r1), "=r"(r2), "=r"(r3) : "r"(addr))
#define MMA16816(d, a0,a1,a2,a3, b0,b1) \
    asm volatile("mma.sync.aligned.m16n8k16.row.col.f32.f16.f16.f32 " \
        "{%0,%1,%2,%3}, {%4,%5,%6,%7}, {%8,%9}, {%0,%1,%2,%3};" \
        : "+f"((d)[0]), "+f"((d)[1]), "+f"((d)[2]), "+f"((d)[3]) \
        : "r"(a0), "r"(a1), "r"(a2), "r"(a3), "r"(b0), "r"(b1))

__device__ __forceinline__ uint32_t fkey(float f) {
    uint32_t u = __float_as_uint(f);
    return (u & 0x80000000u) ? ~u : (u | 0x80000000u);
}
__device__ __forceinline__ void split16(float f, __half& hi, __half& lo) {
    hi = __float2half_rn(f);
    lo = __float2half_rn(f - __half2float(hi));
}

// ---------------- CSR build: edge-order deterministic ----------------------
__global__ void k_hist(const int* __restrict__ dst, int* __restrict__ deg) {
    int e = blockIdx.x * blockDim.x + threadIdx.x;
    if (e < N_EDGES) atomicAdd(&deg[dst[e]], 1);
}
__global__ void k_scan(const int* __restrict__ deg, int* __restrict__ offs) {
    __shared__ int sh[1024];
    __shared__ int carry;
    int tid = threadIdx.x;
    if (tid == 0) { carry = 0; offs[0] = 0; }
    __syncthreads();
    for (int base = 0; base < N_NODES; base += 1024) {
        int v = (base + tid < N_NODES) ? deg[base + tid] : 0;
        sh[tid] = v;
        __syncthreads();
        for (int o = 1; o < 1024; o <<= 1) {
            int t = (tid >= o) ? sh[tid - o] : 0;
            __syncthreads();
            sh[tid] += t;
            __syncthreads();
        }
        if (base + tid < N_NODES) offs[base + tid + 1] = carry + sh[tid];
        __syncthreads();
        if (tid == 0) carry += sh[1023];
        __syncthreads();
    }
}
__global__ void k_fill(const int* __restrict__ src, const int* __restrict__ dst,
                       int* __restrict__ cursor, ull* __restrict__ csrk) {
    int e = blockIdx.x * blockDim.x + threadIdx.x;
    if (e < N_EDGES) {
        int d = dst[e];
        int slot = atomicAdd(&cursor[d], 1);
        csrk[slot] = ((ull)(uint32_t)e << 32) | (uint32_t)src[e];
    }
}
__global__ void k_sortcsr(const int* __restrict__ offs, ull* __restrict__ csrk) {
    int n = blockIdx.x * blockDim.x + threadIdx.x;
    if (n >= N_NODES) return;
    int s = offs[n], e = offs[n + 1];
    for (int i = s + 1; i < e; i++) {
        ull v = csrk[i];
        int j = i - 1;
        while (j >= s && csrk[j] > v) { csrk[j + 1] = csrk[j]; j--; }
        csrk[j + 1] = v;
    }
}

// ---------------- aggregation: fp32, edge order (FROZEN) ------------------
__global__ void k_agg(const float* __restrict__ h, const int* __restrict__ offs,
                      const ull* __restrict__ csrk, float* __restrict__ z) {
    int warp = (blockIdx.x * blockDim.x + threadIdx.x) >> 5;
    int lane = threadIdx.x & 31;
    if (warp >= N_NODES) return;
    const float4* hv = (const float4*)h;
    float4 acc = hv[warp * 32 + lane];
    int s = offs[warp], e = offs[warp + 1];
    for (int i = s; i < e; i++) {
        int sidx = (int)(uint32_t)(__ldg(&csrk[i]) & 0xFFFFFFFFull);
        float4 v = hv[sidx * 32 + lane];
        acc.x += v.x; acc.y += v.y; acc.z += v.z; acc.w += v.w;
    }
    ((float4*)z)[warp * 32 + lane] = acc;
}

// ---------------- fused dual GEMM: t2 = relu(relu(z@W1+b1)@W2+b2) ---------
// M-tile 32, grid 625 (= 20000/32 exactly), occ 3. Per-output FMA chains are
// k=0..127 sequential fp32 — bitwise identical to the two-kernel version.
__global__ __launch_bounds__(256, 3) void k_gemm_fused(
        const float* __restrict__ A, const float* __restrict__ W1,
        const float* __restrict__ b1, const float* __restrict__ W2,
        const float* __restrict__ b2, float* __restrict__ out) {
    __shared__ float As[32][128];   // A tile, then reused for t1
    __shared__ float Ws[32][128];
    int tid = threadIdx.x;
    int tx = tid & 31, ty = tid >> 5;   // tx: col group (4), ty: row group (4)
    int row0 = blockIdx.x * 32;
    float acc[4][4];

    // load A tile (32x128): 1024 float4, 4/thread
#pragma unroll
    for (int it = 0; it < 4; it++) {
        int i = tid + it * 256;
        int r = i >> 5, c4 = i & 31;
        *(float4*)&As[r][c4 * 4] = *(const float4*)&A[(size_t)(row0 + r) * DIM + c4 * 4];
    }

    // ---- GEMM 1 ----
#pragma unroll
    for (int r = 0; r < 4; r++)
#pragma unroll
        for (int c = 0; c < 4; c++) acc[r][c] = 0.f;
    for (int kt = 0; kt < DIM; kt += 32) {
#pragma unroll
        for (int it = 0; it < 4; it++) {
            int i = tid + it * 256;
            int r = i >> 5, c4 = i & 31;
            *(float4*)&Ws[r][c4 * 4] = *(const float4*)&W1[(size_t)(kt + r) * DIM + c4 * 4];
        }
        __syncthreads();
#pragma unroll
        for (int k = 0; k < 32; k++) {
            float4 w = *(float4*)&Ws[k][tx * 4];
#pragma unroll
            for (int r = 0; r < 4; r++) {
                float a = As[ty * 4 + r][kt + k];
                acc[r][0] += a * w.x;
                acc[r][1] += a * w.y;
                acc[r][2] += a * w.z;
                acc[r][3] += a * w.w;
            }
        }
        __syncthreads();
    }
    // t1 = relu(acc + b1) -> overwrite As
    {
        float4 b = *(const float4*)&b1[tx * 4];
        __syncthreads();   // all As reads done before overwrite
#pragma unroll
        for (int r = 0; r < 4; r++) {
            float v0 = fmaxf(acc[r][0] + b.x, 0.f);
            float v1 = fmaxf(acc[r][1] + b.y, 0.f);
            float v2 = fmaxf(acc[r][2] + b.z, 0.f);
            float v3 = fmaxf(acc[r][3] + b.w, 0.f);
            *(float4*)&As[ty * 4 + r][tx * 4] = make_float4(v0, v1, v2, v3);
        }
        __syncthreads();
    }

    // ---- GEMM 2 ----
#pragma unroll
    for (int r = 0; r < 4; r++)
#pragma unroll
        for (int c = 0; c < 4; c++) acc[r][c] = 0.f;
    for (int kt = 0; kt < DIM; kt += 32) {
#pragma unroll
        for (int it = 0; it < 4; it++) {
            int i = tid + it * 256;
            int r = i >> 5, c4 = i & 31;
            *(float4*)&Ws[r][c4 * 4] = *(const float4*)&W2[(size_t)(kt + r) * DIM + c4 * 4];
        }
        __syncthreads();
#pragma unroll
        for (int k = 0; k < 32; k++) {
            float4 w = *(float4*)&Ws[k][tx * 4];
#pragma unroll
            for (int r = 0; r < 4; r++) {
                float a = As[ty * 4 + r][kt + k];
                acc[r][0] += a * w.x;
                acc[r][1] += a * w.y;
                acc[r][2] += a * w.z;
                acc[r][3] += a * w.w;
            }
        }
        __syncthreads();
    }
    {
        float4 b = *(const float4*)&b2[tx * 4];
#pragma unroll
        for (int r = 0; r < 4; r++) {
            int row = row0 + ty * 4 + r;
            float v0 = fmaxf(acc[r][0] + b.x, 0.f);
            float v1 = fmaxf(acc[r][1] + b.y, 0.f);
            float v2 = fmaxf(acc[r][2] + b.z, 0.f);
            float v3 = fmaxf(acc[r][3] + b.w, 0.f);
            *(float4*)&out[(size_t)row * DIM + tx * 4] = make_float4(v0, v1, v2, v3);
        }
    }
}

// ---------------- head GEMM fp32 (FROZEN, small M) -------------------------
__global__ __launch_bounds__(256) void k_gemm(
        const float* __restrict__ A, const float* __restrict__ W,
        const float* __restrict__ bias, float* __restrict__ out,
        int M, int doRelu) {
    __shared__ float As[64][32];
    __shared__ float Ws[32][128];
    int tid = threadIdx.x;
    int tx = tid & 31, ty = tid >> 5;
    int row0 = blockIdx.x * 64;
    float acc[8][4];
#pragma unroll
    for (int r = 0; r < 8; r++)
#pragma unroll
        for (int c = 0; c < 4; c++) acc[r][c] = 0.f;

    for (int kt = 0; kt < DIM; kt += 32) {
#pragma unroll
        for (int it = 0; it < 2; it++) {
            int i = tid + it * 256;
            int r = i >> 3, c4 = i & 7;
            int row = row0 + r;
            float4 v = make_float4(0.f, 0.f, 0.f, 0.f);
            if (row < M) v = *(const float4*)&A[row * DIM + kt + c4 * 4];
            *(float4*)&As[r][c4 * 4] = v;
        }
#pragma unroll
        for (int it = 0; it < 4; it++) {
            int i = tid + it * 256;
            int r = i >> 5, c4 = i & 31;
            *(float4*)&Ws[r][c4 * 4] = *(const float4*)&W[(kt + r) * DIM + c4 * 4];
        }
        __syncthreads();
#pragma unroll
        for (int k = 0; k < 32; k++) {
            float4 w = *(float4*)&Ws[k][tx * 4];
#pragma unroll
            for (int r = 0; r < 8; r++) {
                float a = As[ty * 8 + r][k];
                acc[r][0] += a * w.x;
                acc[r][1] += a * w.y;
                acc[r][2] += a * w.z;
                acc[r][3] += a * w.w;
            }
        }
        __syncthreads();
    }
    float4 b = *(const float4*)&bias[tx * 4];
#pragma unroll
    for (int r = 0; r < 8; r++) {
        int row = row0 + ty * 8 + r;
        if (row < M) {
            float v0 = acc[r][0] + b.x;
            float v1 = acc[r][1] + b.y;
            float v2 = acc[r][2] + b.z;
            float v3 = acc[r][3] + b.w;
            if (doRelu) {
                v0 = fmaxf(v0, 0.f); v1 = fmaxf(v1, 0.f);
                v2 = fmaxf(v2, 0.f); v3 = fmaxf(v3, 0.f);
            }
            *(float4*)&out[row * DIM + tx * 4] = make_float4(v0, v1, v2, v3);
        }
    }
}

// ---------------- BN stats (FROZEN) ---------------------------------------
__global__ void k_stats(const float* __restrict__ t2, float* __restrict__ pstats) {
    __shared__ float ss[256], qq[256];
    int tid = threadIdx.x;
    int col = tid & 127, half = tid >> 7;
    float s = 0.f, q = 0.f;
    int row0 = blockIdx.x * 128;
    for (int i = half; i < 128; i += 2) {
        int r = row0 + i;
        if (r < N_NODES) {
            float v = t2[(size_t)r * DIM + col];
            s += v; q += v * v;
        }
    }
    ss[tid] = s; qq[tid] = q;
    __syncthreads();
    if (tid < 128) {
        pstats[blockIdx.x * 256 + tid]       = ss[tid] + ss[tid + 128];
        pstats[blockIdx.x * 256 + 128 + tid] = qq[tid] + qq[tid + 128];
    }
}

__global__ void k_bnfin(const float* __restrict__ pstats,
                        float* __restrict__ mean, float* __restrict__ invstd) {
    int d = threadIdx.x;
    float s = 0.f, q = 0.f;
    for (int b = 0; b < STAT_BLOCKS; b++) {
        s += pstats[b * 256 + d];
        q += pstats[b * 256 + 128 + d];
    }
    float mu = s / (float)N_NODES;
    float var = q / (float)N_NODES - mu * mu;
    mean[d] = mu;
    invstd[d] = rsqrtf(var + BN_EPS);
}

__global__ void k_bnapply(const float* __restrict__ z, const float* __restrict__ mean,
                          const float* __restrict__ invstd, const float* __restrict__ gamma,
                          const float* __restrict__ beta, float* __restrict__ h) {
    int i = blockIdx.x * blockDim.x + threadIdx.x;
    if (i < N_NODES * DIM) {
        int d = i & (DIM - 1);
        h[i] = (z[i] - mean[d]) * invstd[d] * gamma[d] + beta[d];
    }
}

// ---------------- VQ: codebook norms ----------------
__global__ void k_cnorm(const float* __restrict__ cb, float* __restrict__ cnorm) {
    int warp = (blockIdx.x * blockDim.x + threadIdx.x) >> 5;
    int lane = threadIdx.x & 31;
    if (warp >= CODEBOOK_PAD) return;
    if (warp >= CODEBOOK_N) { if (lane == 0) cnorm[warp] = 1e30f; return; }
    float4 v = ((const float4*)cb)[warp * 32 + lane];
    float s = v.x * v.x + v.y * v.y + v.z * v.z + v.w * v.w;
#pragma unroll
    for (int o = 16; o; o >>= 1) s += __shfl_xor_sync(0xffffffffu, s, o);
    if (lane == 0) cnorm[warp] = s;
}

// ---------------- split codebook: [c_hi | c_lo] fp16, K=256 ----------------
__global__ void k_split_cb(const float* __restrict__ cb, __half* __restrict__ cbs) {
    int gid = blockIdx.x * blockDim.x + threadIdx.x;
    if (gid >= CODEBOOK_PAD * DIM) return;
    int j = gid >> 7, d = gid & 127;
    float v = (j < CODEBOOK_N) ? cb[j * DIM + d] : 0.f;
    __half hi, lo; split16(v, hi, lo);
    __half* row = cbs + (size_t)j * VQ_K;
    row[d] = hi;
    row[128 + d] = lo;
}

// ---------------- VQ main: segment-split fp16 3-term GEMM-argmin -----------
__global__ __launch_bounds__(256, 2) void k_vq_mma(
        const float* __restrict__ h, const __half* __restrict__ cbs,
        const float* __restrict__ cnorm,
        float* __restrict__ pd1, float* __restrict__ pd2, int* __restrict__ pj1) {
    extern __shared__ __align__(16) char dyn[];
    __half* As = (__half*)dyn;                 // [64][264]
    __half* Bs = As + 64 * AS_STRIDE;          // [4][64][72]
    float* cns = (float*)(Bs + 4 * BS_BUF_H);  // [64]
    float* rD1 = cns + 64;                     // [64][4]
    float* rD2 = rD1 + 256;
    int*   rJ1 = (int*)(rD2 + 256);
    uint32_t As_u = smem_u32(As);
    uint32_t Bs_u = smem_u32(Bs);

    int tid = threadIdx.x, lane = tid & 31, wid = tid >> 5;
    int warp_m = wid & 1, warp_n = wid >> 1;   // 2m x 4n
    int node0 = blockIdx.x * 64;
    int seg = blockIdx.y;
    int cstart = seg * VQ_CPS;
    int cend = cstart + VQ_CPS;

    // ---- A: [x_hi | x_lo]; 4 threads/row ----
    {
        int r = tid >> 2, q = tid & 3;
        bool valid = (node0 + r) < N_NODES;
        const float4* hp = (const float4*)(h + (size_t)(valid ? node0 + r : 0) * DIM);
        __half* arow = As + r * AS_STRIDE;
#pragma unroll
        for (int v = 0; v < 8; v++) {
            float4 f = valid ? hp[q * 8 + v] : make_float4(0.f, 0.f, 0.f, 0.f);
            __half hx, lx, hy, ly, hz, lz, hw, lw;
            split16(f.x, hx, lx); split16(f.y, hy, ly);
            split16(f.z, hz, lz); split16(f.w, hw, lw);
            int col = q * 32 + v * 4;
            arow[col + 0] = hx; arow[col + 1] = hy; arow[col + 2] = hz; arow[col + 3] = hw;
            arow[128 + col + 0] = lx; arow[128 + col + 1] = ly;
            arow[128 + col + 2] = lz; arow[128 + col + 3] = lw;
        }
    }

#pragma unroll
    for (int pc = 0; pc < 2; pc++) {
        int ci = cstart + pc;
        const __half* base = cbs + (size_t)(ci >> 2) * 64 * VQ_K + (ci & 3) * 64;
#pragma unroll
        for (int it = 0; it < 2; it++) {
            int i = tid + it * 256;
            int row = i >> 3, c16 = i & 7;
            CP_ASYNC16(Bs_u + (uint32_t)(pc * BS_BUF_H + row * BS_STRIDE + c16 * 8) * 2,
                       base + (size_t)row * VQ_K + c16 * 8);
        }
        CP_COMMIT();
    }

    float d1v[2][2] = {{1e38f, 1e38f}, {1e38f, 1e38f}};
    float d2v[2][2] = {{1e38f, 1e38f}, {1e38f, 1e38f}};
    int   j1v[2][2] = {{0, 0}, {0, 0}};
    int lr = lane & 7, g = lane >> 3;
    float acc[2][2][4];

    for (int ci = cstart; ci < cend; ci++) {
        int t = ci >> 2, c = ci & 3;
        int buf = ci & 3;
        if (c == 0) {
#pragma unroll
            for (int mt = 0; mt < 2; mt++)
#pragma unroll
                for (int hf = 0; hf < 2; hf++)
#pragma unroll
                    for (int r = 0; r < 4; r++) acc[mt][hf][r] = 0.f;
        }
        if (ci + 2 < cend) {
            int pidx = ci + 2;
            int pbuf = pidx & 3;
            const __half* base = cbs + (size_t)(pidx >> 2) * 64 * VQ_K + (pidx & 3) * 64;
#pragma unroll
            for (int it = 0; it < 2; it++) {
                int i = tid + it * 256;
                int row = i >> 3, c16 = i & 7;
                CP_ASYNC16(Bs_u + (uint32_t)(pbuf * BS_BUF_H + row * BS_STRIDE + c16 * 8) * 2,
                           base + (size_t)row * VQ_K + c16 * 8);
            }
            CP_COMMIT();
            CP_WAIT(2);
        } else {
            CP_WAIT(0);
        }
        __syncthreads();
        if (c == 0 && tid < 64) cns[tid] = __ldg(&cnorm[t * 64 + tid]);

        uint32_t bbase = Bs_u + (uint32_t)(buf * BS_BUF_H) * 2;
        if (c < 2) {
#pragma unroll
            for (int kk = 0; kk < 4; kk++) {
                int kcol = c * 64 + kk * 16;
                uint32_t ah0[2], ah1[2], ah2[2], ah3[2];
                uint32_t al0[2], al1[2], al2[2], al3[2];
#pragma unroll
                for (int mt = 0; mt < 2; mt++) {
                    uint32_t abase = As_u +
                        (uint32_t)((warp_m * 32 + mt * 16 + lr + ((g & 1) << 3)) * AS_STRIDE
                                   + kcol + ((g >> 1) << 3)) * 2;
                    LDSM4(ah0[mt], ah1[mt], ah2[mt], ah3[mt], abase);
                    LDSM4(al0[mt], al1[mt], al2[mt], al3[mt], abase + 128 * 2);
                }
                uint32_t b0, b1, b2, b3;
                uint32_t baddr = bbase +
                    (uint32_t)((warp_n * 16 + lr + ((g >> 1) << 3)) * BS_STRIDE
                               + kk * 16 + ((g & 1) << 3)) * 2;
                LDSM4(b0, b1, b2, b3, baddr);
#pragma unroll
                for (int mt = 0; mt < 2; mt++) {
                    MMA16816(acc[mt][0], ah0[mt], ah1[mt], ah2[mt], ah3[mt], b0, b1);
                    MMA16816(acc[mt][1], ah0[mt], ah1[mt], ah2[mt], ah3[mt], b2, b3);
                    MMA16816(acc[mt][0], al0[mt], al1[mt], al2[mt], al3[mt], b0, b1);
                    MMA16816(acc[mt][1], al0[mt], al1[mt], al2[mt], al3[mt], b2, b3);
                }
            }
        } else {
            int cc = c - 2;
#pragma unroll
            for (int kk = 0; kk < 4; kk++) {
                int kcol = cc * 64 + kk * 16;
                uint32_t ah0[2], ah1[2], ah2[2], ah3[2];
#pragma unroll
                for (int mt = 0; mt < 2; mt++) {
                    uint32_t abase = As_u +
                        (uint32_t)((warp_m * 32 + mt * 16 + lr + ((g & 1) << 3)) * AS_STRIDE
                                   + kcol + ((g >> 1) << 3)) * 2;
                    LDSM4(ah0[mt], ah1[mt], ah2[mt], ah3[mt], abase);
                }
                uint32_t b0, b1, b2, b3;
                uint32_t baddr = bbase +
                    (uint32_t)((warp_n * 16 + lr + ((g >> 1) << 3)) * BS_STRIDE
                               + kk * 16 + ((g & 1) << 3)) * 2;
                LDSM4(b0, b1, b2, b3, baddr);
#pragma unroll
                for (int mt = 0; mt < 2; mt++) {
                    MMA16816(acc[mt][0], ah0[mt], ah1[mt], ah2[mt], ah3[mt], b0, b1);
                    MMA16816(acc[mt][1], ah0[mt], ah1[mt], ah2[mt], ah3[mt], b2, b3);
                }
            }
        }

        if (c == VQ_CPT - 1) {
            int cb0 = warp_n * 16;
            int lcol = 2 * (lane & 3);
#pragma unroll
            for (int hf = 0; hf < 2; hf++) {
                int cloc = cb0 + hf * 8 + lcol;
                float cn0 = cns[cloc], cn1 = cns[cloc + 1];
                int code = t * 64 + cloc;
#pragma unroll
                for (int mt = 0; mt < 2; mt++)
#pragma unroll
                    for (int rs = 0; rs < 2; rs++) {
                        float dA = cn0 - 2.f * acc[mt][hf][rs * 2 + 0];
                        float dB = cn1 - 2.f * acc[mt][hf][rs * 2 + 1];
                        if (dA < d1v[mt][rs]) { d2v[mt][rs] = d1v[mt][rs]; d1v[mt][rs] = dA; j1v[mt][rs] = code; }
                        else if (dA < d2v[mt][rs]) d2v[mt][rs] = dA;
                        if (dB < d1v[mt][rs]) { d2v[mt][rs] = d1v[mt][rs]; d1v[mt][rs] = dB; j1v[mt][rs] = code + 1; }
                        else if (dB < d2v[mt][rs]) d2v[mt][rs] = dB;
                    }
            }
        }
    }

#pragma unroll
    for (int o = 1; o <= 2; o <<= 1) {
#pragma unroll
        for (int mt = 0; mt < 2; mt++)
#pragma unroll
            for (int rs = 0; rs < 2; rs++) {
                float od1 = __shfl_xor_sync(0xffffffffu, d1v[mt][rs], o);
                float od2 = __shfl_xor_sync(0xffffffffu, d2v[mt][rs], o);
                int   oj  = __shfl_xor_sync(0xffffffffu, j1v[mt][rs], o);
                if (od1 < d1v[mt][rs] || (od1 == d1v[mt][rs] && oj < j1v[mt][rs])) {
                    d2v[mt][rs] = fminf(d1v[mt][rs], od2);
                    d1v[mt][rs] = od1; j1v[mt][rs] = oj;
                } else {
                    d2v[mt][rs] = fminf(d2v[mt][rs], od1);
                }
            }
    }
    __syncthreads();
    if ((lane & 3) == 0) {
#pragma unroll
        for (int mt = 0; mt < 2; mt++)
#pragma unroll
            for (int rs = 0; rs < 2; rs++) {
                int nl = warp_m * 32 + mt * 16 + rs * 8 + (lane >> 2);
                rD1[nl * 4 + warp_n] = d1v[mt][rs];
                rD2[nl * 4 + warp_n] = d2v[mt][rs];
                rJ1[nl * 4 + warp_n] = j1v[mt][rs];
            }
    }
    __syncthreads();
    if (tid < 64) {
        float f1 = rD1[tid * 4], f2 = rD2[tid * 4];
        int fj = rJ1[tid * 4];
#pragma unroll
        for (int wn = 1; wn < 4; wn++) {
            float b1 = rD1[tid * 4 + wn], b2 = rD2[tid * 4 + wn];
            int bj = rJ1[tid * 4 + wn];
            if (b1 < f1 || (b1 == f1 && bj < fj)) {
                f2 = fminf(f1, b2); f1 = b1; fj = bj;
            } else {
                f2 = fminf(f2, b1);
            }
        }
        int slot = seg * NODE_PAD + node0 + tid;
        pd1[slot] = f1; pd2[slot] = f2; pj1[slot] = fj;
    }
}

// ---------------- merge segments (deterministic, fixed order) --------------
__global__ void k_vqmerge(const float* __restrict__ pd1, const float* __restrict__ pd2,
                          const int* __restrict__ pj1, int* __restrict__ outidx,
                          int* __restrict__ flaglist, int* __restrict__ flagcnt) {
    int n = blockIdx.x * blockDim.x + threadIdx.x;
    if (n >= N_NODES) return;
    float f1 = pd1[n], f2 = pd2[n];
    int fj = pj1[n];
#pragma unroll
    for (int s = 1; s < VQ_SEGS; s++) {
        float b1 = pd1[s * NODE_PAD + n], b2 = pd2[s * NODE_PAD + n];
        int bj = pj1[s * NODE_PAD + n];
        if (b1 < f1 || (b1 == f1 && bj < fj)) {
            f2 = fminf(f1, b2); f1 = b1; fj = bj;
        } else {
            f2 = fminf(f2, b1);
        }
    }
    outidx[n] = fj;
    if (f2 - f1 < VQ_MARGIN) {
        int p = atomicAdd(flagcnt, 1);
        flaglist[p] = n;
    }
}

// ---------------- exact fp32 rescue (order-invariant via atomicMin) --------
__global__ __launch_bounds__(128) void k_rescue(
        const float* __restrict__ h, const float* __restrict__ cb,
        const float* __restrict__ cnorm, const int* __restrict__ flaglist,
        const int* __restrict__ flagcnt, ull* __restrict__ best) {
    extern __shared__ __align__(16) float rs[];
    float* cs   = rs;
    float* hrow = cs + 128 * 128;
    float* rd   = hrow + 128;
    int*   rj   = (int*)(rd + 128);
    int tid = threadIdx.x;
    int c0 = blockIdx.x * 128;
    int code = c0 + tid;
#pragma unroll
    for (int it = 0; it < 32; it++) {
        int i = tid + it * 128;
        int row = i >> 5, c4 = i & 31;
        float4 v = make_float4(0.f, 0.f, 0.f, 0.f);
        if (c0 + row < CODEBOOK_N) v = __ldg(&((const float4*)cb)[(size_t)(c0 + row) * 32 + c4]);
        *(float4*)&cs[row * 128 + c4 * 4] = v;
    }
    float cn = cnorm[code];
    __syncthreads();
    int cnt = *flagcnt;
    const float4* crow4 = (const float4*)&cs[tid * 128];
    const float4* h4 = (const float4*)hrow;
    for (int f = 0; f < cnt; f++) {
        int node = flaglist[f];
        if (tid < 32) ((float4*)hrow)[tid] = ((const float4*)(h + (size_t)node * DIM))[tid];
        __syncthreads();
        float dot = 0.f;
#pragma unroll
        for (int k4 = 0; k4 < 32; k4++) {
            int i = (k4 + tid) & 31;
            float4 cv = crow4[i];
            float4 hv = h4[i];
            dot += cv.x * hv.x + cv.y * hv.y + cv.z * hv.z + cv.w * hv.w;
        }
        float d = cn - 2.f * dot;
        rd[tid] = d; rj[tid] = code;
        __syncthreads();
        for (int o = 64; o; o >>= 1) {
            if (tid < o) {
                float od = rd[tid + o]; int oc = rj[tid + o];
                if (od < rd[tid] || (od == rd[tid] && oc < rj[tid])) {
                    rd[tid] = od; rj[tid] = oc;
                }
            }
            __syncthreads();
        }
        if (tid == 0) {
            ull key = ((ull)fkey(rd[0]) << 32) | (uint32_t)rj[0];
            atomicMin(&best[node], key);
        }
        __syncthreads();
    }
}

__global__ void k_flagapply(const int* __restrict__ flaglist, const int* __restrict__ flagcnt,
                            const ull* __restrict__ best, int* __restrict__ outidx) {
    int cnt = *flagcnt;
    for (int i = blockIdx.x * blockDim.x + threadIdx.x; i < cnt; i += gridDim.x * blockDim.x) {
        int node = flaglist[i];
        outidx[node] = (int)(best[node] & 0xFFFFFFFFull);
    }
}

// ---------------- final per-node ----------------
__global__ void k_final(const float* __restrict__ h, const float* __restrict__ cb,
                        const int* __restrict__ idx, const float* __restrict__ score,
                        const int* __restrict__ batch, float* __restrict__ cacc,
                        float* __restrict__ sacc, float* __restrict__ cmt) {
    __shared__ float sh[256];
    int i = blockIdx.x * blockDim.x + threadIdx.x;
    float local = 0.f;
    if (i < N_NODES * DIM) {
        int node = i >> 7, d = i & 127;
        float hv = h[i];
        float q = cb[idx[node] * DIM + d];
        float diff = q - hv;
        local = diff * diff;
        float res = hv + q;
        float sc = score[node];
        int b = batch[node];
        atomicAdd(&cacc[b * DIM + d], res * sc);
        atomicAdd(&sacc[b * DIM + d], res * (1.f - sc));
    }
    sh[threadIdx.x] = local;
    __syncthreads();
    for (int o = 128; o; o >>= 1) {
        if (threadIdx.x < o) sh[threadIdx.x] += sh[threadIdx.x + o];
        __syncthreads();
    }
    if (threadIdx.x == 0) atomicAdd(cmt, sh[0]);
}

__global__ void k_cmtfin(const float* __restrict__ cmt, float* __restrict__ out) {
    out[2 * N_GRAPHS * DIM] = COMMIT_W * cmt[0] / (float)(N_NODES * DIM);
}

// ---------------- launcher ----------------
extern "C" void kernel_launch(void* const* d_in, const int* in_sizes, int n_in,
                              void* d_out, int out_size) {
    const float* x        = (const float*)d_in[0];
    const int*   ei       = (const int*)  d_in[1];
    const int*   batch    = (const int*)  d_in[2];
    const float* score    = (const float*)d_in[3];
    const float* cW1      = (const float*)d_in[4];
    const float* cb1      = (const float*)d_in[5];
    const float* cW2      = (const float*)d_in[6];
    const float* cb2      = (const float*)d_in[7];
    const float* bng      = (const float*)d_in[8];
    const float* bnb      = (const float*)d_in[9];
    const float* codebook = (const float*)d_in[10];
    const float* fc1W     = (const float*)d_in[11];
    const float* fc1b     = (const float*)d_in[12];
    const float* fc2W     = (const float*)d_in[13];
    const float* fc2b     = (const float*)d_in[14];
    float* out = (float*)d_out;
    const int* src = ei;
    const int* dst = ei + N_EDGES;

    void *p_z, *p_t2, *p_h, *p_deg, *p_offs, *p_cursor, *p_csrk;
    void *p_pstats, *p_mean, *p_invstd, *p_cnorm, *p_idx, *p_cacc, *p_sacc, *p_cmt;
    void *p_cbs, *p_pd1, *p_pd2, *p_pj1, *p_flag, *p_fcnt, *p_best;
    cudaGetSymbolAddress(&p_z, g_z);
    cudaGetSymbolAddress(&p_t2, g_t2);
    cudaGetSymbolAddress(&p_h, g_h);
    cudaGetSymbolAddress(&p_deg, g_deg);
    cudaGetSymbolAddress(&p_offs, g_offs);
    cudaGetSymbolAddress(&p_cursor, g_cursor);
    cudaGetSymbolAddress(&p_csrk, g_csrk);
    cudaGetSymbolAddress(&p_pstats, g_pstats);
    cudaGetSymbolAddress(&p_mean, g_mean);
    cudaGetSymbolAddress(&p_invstd, g_invstd);
    cudaGetSymbolAddress(&p_cnorm, g_cnorm);
    cudaGetSymbolAddress(&p_idx, g_idx);
    cudaGetSymbolAddress(&p_cacc, g_cacc);
    cudaGetSymbolAddress(&p_sacc, g_sacc);
    cudaGetSymbolAddress(&p_cmt, g_cmt);
    cudaGetSymbolAddress(&p_cbs, g_cbs);
    cudaGetSymbolAddress(&p_pd1, g_pd1);
    cudaGetSymbolAddress(&p_pd2, g_pd2);
    cudaGetSymbolAddress(&p_pj1, g_pj1);
    cudaGetSymbolAddress(&p_flag, g_flaglist);
    cudaGetSymbolAddress(&p_fcnt, g_flagcnt);
    cudaGetSymbolAddress(&p_best, g_best);

    const int SMEM_VQ = 64 * AS_STRIDE * 2 + 4 * BS_BUF_H * 2 + 64 * 4 + 256 * 4 * 3;
    const int SMEM_RESCUE = 128 * 128 * 4 + 128 * 4 * 3;
    static bool attr_set = false;
    if (!attr_set) {
        cudaFuncSetAttribute(k_vq_mma, cudaFuncAttributeMaxDynamicSharedMemorySize, SMEM_VQ);
        cudaFuncSetAttribute(k_rescue, cudaFuncAttributeMaxDynamicSharedMemorySize, SMEM_RESCUE);
        attr_set = true;
    }

    // CSR build, canonicalized to exact EDGE order (FROZEN)
    cudaMemsetAsync(p_deg, 0, N_NODES * sizeof(int));
    k_hist<<<(N_EDGES + 255) / 256, 256>>>(dst, (int*)p_deg);
    k_scan<<<1, 1024>>>((const int*)p_deg, (int*)p_offs);
    cudaMemcpyAsync(p_cursor, p_offs, N_NODES * sizeof(int), cudaMemcpyDeviceToDevice);
    k_fill<<<(N_EDGES + 255) / 256, 256>>>(src, dst, (int*)p_cursor, (ull*)p_csrk);
    k_sortcsr<<<(N_NODES + 127) / 128, 128>>>((const int*)p_offs, (ull*)p_csrk);

    // codebook prep
    k_cnorm<<<(CODEBOOK_PAD * 32 + 255) / 256, 256>>>(codebook, (float*)p_cnorm);
    k_split_cb<<<(CODEBOOK_PAD * DIM + 255) / 256, 256>>>(codebook, (__half*)p_cbs);

    // MLP chain: fused dual-GEMM per layer (bitwise-identical h)
    const float* h = x;
    for (int l = 0; l < N_LAYERS; l++) {
        k_agg<<<(N_NODES * 32 + 255) / 256, 256>>>(h, (const int*)p_offs,
                                                   (const ull*)p_csrk, (float*)p_z);
        k_gemm_fused<<<N_NODES / 32, 256>>>(
            (const float*)p_z, cW1 + l * DIM * DIM, cb1 + l * DIM,
            cW2 + l * DIM * DIM, cb2 + l * DIM, (float*)p_t2);
        k_stats<<<STAT_BLOCKS, 256>>>((const float*)p_t2, (float*)p_pstats);
        k_bnfin<<<1, 128>>>((const float*)p_pstats, (float*)p_mean, (float*)p_invstd);
        k_bnapply<<<(N_NODES * DIM + 255) / 256, 256>>>(
            (const float*)p_t2, (const float*)p_mean, (const float*)p_invstd,
            bng + l * DIM, bnb + l * DIM, (float*)p_h);
        h = (const float*)p_h;
    }

    // VQ: segment-split tensor-core search + deterministic merge + exact rescue
    cudaMemsetAsync(p_fcnt, 0, sizeof(int));
    cudaMemsetAsync(p_best, 0xFF, N_NODES * sizeof(ull));
    k_vq_mma<<<dim3(VQ_MBLK, VQ_SEGS), 256, SMEM_VQ>>>(
        (const float*)p_h, (const __half*)p_cbs, (const float*)p_cnorm,
        (float*)p_pd1, (float*)p_pd2, (int*)p_pj1);
    k_vqmerge<<<(N_NODES + 255) / 256, 256>>>(
        (const float*)p_pd1, (const float*)p_pd2, (const int*)p_pj1,
        (int*)p_idx, (int*)p_flag, (int*)p_fcnt);
    k_rescue<<<CODEBOOK_PAD / 128, 128, SMEM_RESCUE>>>(
        (const float*)p_h, codebook, (const float*)p_cnorm,
        (const int*)p_flag, (const int*)p_fcnt, (ull*)p_best);
    k_flagapply<<<40, 256>>>((const int*)p_flag, (const int*)p_fcnt,
                             (const ull*)p_best, (int*)p_idx);

    cudaMemsetAsync(p_cacc, 0, N_GRAPHS * DIM * sizeof(float));
    cudaMemsetAsync(p_sacc, 0, N_GRAPHS * DIM * sizeof(float));
    cudaMemsetAsync(p_cmt, 0, sizeof(float));
    k_final<<<(N_NODES * DIM + 255) / 256, 256>>>(
        (const float*)p_h, codebook, (const int*)p_idx, score, batch,
        (float*)p_cacc, (float*)p_sacc, (float*)p_cmt);

    k_gemm<<<(N_GRAPHS + 63) / 64, 256>>>((const float*)p_cacc, fc1W, fc1b,
                                          out, N_GRAPHS, 1);
    k_gemm<<<(N_GRAPHS + 63) / 64, 256>>>((const float*)p_sacc, fc2W, fc2b,
                                          out + N_GRAPHS * DIM, N_GRAPHS, 1);
    k_cmtfin<<<1, 1>>>((const float*)p_cmt, out);
}